// round 1
// baseline (speedup 1.0000x reference)
#include <cuda_runtime.h>
#include <cuda_bf16.h>
#include <math.h>

// Problem constants
#define B_  2
#define S_  2048
#define E_  1024
#define H_  16
#define HD_ 64
#define M_TOK (B_ * S_)          // 4096
#define QKV_N (3 * E_)           // 3072

// ---------------------------------------------------------------------------
// Scratch (no allocation allowed -> __device__ globals)
// ---------------------------------------------------------------------------
__device__ float g_qkv[M_TOK * QKV_N];            // [4096, 3072]
__device__ float g_O1[B_ * H_ * S_ * HD_];        // [b,h,s,d]
__device__ float g_O2[B_ * H_ * S_ * HD_];
__device__ float g_X2[B_ * S_ * E_];              // scrambled layout, pre-wo
__device__ float g_lam;

// ---------------------------------------------------------------------------
// SGEMM: C[M,N] = A[M,K] @ B[K,N], row-major, fp32.
// 128x128 block tile, BK=8, 256 threads, 8x8 per thread.
// ---------------------------------------------------------------------------
__global__ __launch_bounds__(256) void sgemm_kernel(
    const float* __restrict__ A, const float* __restrict__ Bm,
    float* __restrict__ C, int M, int N, int K)
{
    __shared__ float As[8][128];
    __shared__ float Bs[8][128];

    const int tid = threadIdx.x;
    const int bm = blockIdx.y * 128;
    const int bn = blockIdx.x * 128;

    const int aRow = tid >> 1;            // 0..127
    const int aCol = (tid & 1) << 2;      // 0 or 4
    const int bRow = tid >> 5;            // 0..7
    const int bCol = (tid & 31) << 2;     // 0..124

    const float* Aptr = A + (size_t)(bm + aRow) * K + aCol;
    const float* Bptr = Bm + (size_t)bRow * N + bn + bCol;

    const int tr = ((tid >> 4)) << 3;     // 0..120
    const int tc = (tid & 15) << 3;

    float acc[8][8];
#pragma unroll
    for (int i = 0; i < 8; i++)
#pragma unroll
        for (int j = 0; j < 8; j++) acc[i][j] = 0.f;

    for (int k0 = 0; k0 < K; k0 += 8) {
        float4 av = *(const float4*)(Aptr + k0);
        As[aCol + 0][aRow] = av.x;
        As[aCol + 1][aRow] = av.y;
        As[aCol + 2][aRow] = av.z;
        As[aCol + 3][aRow] = av.w;
        *(float4*)(&Bs[bRow][bCol]) = *(const float4*)(Bptr + (size_t)k0 * N);
        __syncthreads();

#pragma unroll
        for (int kk = 0; kk < 8; kk++) {
            float ra[8], rb[8];
#pragma unroll
            for (int i = 0; i < 8; i++) ra[i] = As[kk][tr + i];
#pragma unroll
            for (int j = 0; j < 8; j++) rb[j] = Bs[kk][tc + j];
#pragma unroll
            for (int i = 0; i < 8; i++)
#pragma unroll
                for (int j = 0; j < 8; j++) acc[i][j] += ra[i] * rb[j];
        }
        __syncthreads();
    }

#pragma unroll
    for (int i = 0; i < 8; i++) {
        float* Crow = C + (size_t)(bm + tr + i) * N + bn + tc;
        *(float4*)(Crow)     = make_float4(acc[i][0], acc[i][1], acc[i][2], acc[i][3]);
        *(float4*)(Crow + 4) = make_float4(acc[i][4], acc[i][5], acc[i][6], acc[i][7]);
    }
}

// ---------------------------------------------------------------------------
// Lambda scalar: lam = exp(lq1.lk1) - exp(lq2.lk2) + 0.8
// ---------------------------------------------------------------------------
__global__ void lambda_kernel(const float* __restrict__ lq1, const float* __restrict__ lq2,
                              const float* __restrict__ lk1, const float* __restrict__ lk2)
{
    if (threadIdx.x == 0) {
        float d1 = 0.f, d2 = 0.f;
        for (int i = 0; i < HD_; i++) { d1 += lq1[i] * lk1[i]; d2 += lq2[i] * lk2[i]; }
        g_lam = expf(d1) - expf(d2) + 0.8f;
    }
}

// ---------------------------------------------------------------------------
// Flash attention, one half (d0 = 0 or 32 selects q/k half; V is full 64).
// Block = 128 query rows (1 per thread) of one (b,h); loops over K/V tiles of 64.
// grid = (S/128, B*H)
// ---------------------------------------------------------------------------
__global__ __launch_bounds__(128) void attn_kernel(
    const float* __restrict__ qkv, float* __restrict__ Oout, int d0)
{
    __shared__ float Ks[64][32];
    __shared__ float Vs[64][64];

    const int bh = blockIdx.y;
    const int b = bh >> 4, h = bh & 15;
    const int tid = threadIdx.x;
    const int qs = blockIdx.x * 128 + tid;
    const float* base = qkv + (size_t)b * S_ * QKV_N;

    // q scaled by 1/sqrt(64) * log2(e), softmax done in base 2
    float q[32];
    {
        const float* qp = base + (size_t)qs * QKV_N + h * HD_ + d0;
        const float sc = 0.125f * 1.4426950408889634f;
#pragma unroll
        for (int i = 0; i < 32; i += 4) {
            float4 v = *(const float4*)(qp + i);
            q[i] = v.x * sc; q[i + 1] = v.y * sc; q[i + 2] = v.z * sc; q[i + 3] = v.w * sc;
        }
    }

    float m = -1e30f, l = 0.f;
    float o[64];
#pragma unroll
    for (int d = 0; d < 64; d++) o[d] = 0.f;

    const int koff = E_ + h * HD_ + d0;
    const int voff = 2 * E_ + h * HD_;

    for (int t0 = 0; t0 < S_; t0 += 64) {
        __syncthreads();
#pragma unroll
        for (int it = 0; it < 4; it++) {           // K tile: 64 x 32 floats
            int f = tid + it * 128;
            int j = f >> 3, dc = (f & 7) << 2;
            *(float4*)&Ks[j][dc] =
                *(const float4*)(base + (size_t)(t0 + j) * QKV_N + koff + dc);
        }
#pragma unroll
        for (int it = 0; it < 8; it++) {           // V tile: 64 x 64 floats
            int f = tid + it * 128;
            int j = f >> 4, dc = (f & 15) << 2;
            *(float4*)&Vs[j][dc] =
                *(const float4*)(base + (size_t)(t0 + j) * QKV_N + voff + dc);
        }
        __syncthreads();

#pragma unroll
        for (int c0 = 0; c0 < 64; c0 += 16) {
            float s[16];
#pragma unroll
            for (int j = 0; j < 16; j++) {
                float acc = 0.f;
#pragma unroll
                for (int d = 0; d < 32; d++) acc += q[d] * Ks[c0 + j][d];
                s[j] = acc;
            }
            float tm = s[0];
#pragma unroll
            for (int j = 1; j < 16; j++) tm = fmaxf(tm, s[j]);
            float mn = fmaxf(m, tm);
            float corr = exp2f(m - mn);
            l *= corr;
#pragma unroll
            for (int d = 0; d < 64; d++) o[d] *= corr;
#pragma unroll
            for (int j = 0; j < 16; j++) {
                float p = exp2f(s[j] - mn);
                l += p;
#pragma unroll
                for (int d = 0; d < 64; d++) o[d] += p * Vs[c0 + j][d];
            }
            m = mn;
        }
    }

    const float inv = 1.f / l;
    float* op = Oout + ((size_t)bh * S_ + qs) * HD_;
#pragma unroll
    for (int d = 0; d < 64; d += 4)
        *(float4*)(op + d) = make_float4(o[d] * inv, o[d + 1] * inv, o[d + 2] * inv, o[d + 3] * inv);
}

// ---------------------------------------------------------------------------
// Combine: out = O1 - lam*O2, per-head RMSNorm, *norm_w*(1-0.8),
// scatter into the reference's scrambled layout:
//   X2[b][d*32 + h*2 + (s>>10)][s & 1023]
// One warp per (b,h,s) row; lane handles d = lane and lane+32.
// ---------------------------------------------------------------------------
__global__ __launch_bounds__(256) void combine_kernel(
    const float* __restrict__ O1, const float* __restrict__ O2,
    const float* __restrict__ normw, float* __restrict__ X2)
{
    const int r = blockIdx.x * 8 + (threadIdx.x >> 5);   // row in [0, B*H*S)
    const int lane = threadIdx.x & 31;
    const int bh = r >> 11;
    const int s = r & 2047;
    const int b = bh >> 4, h = bh & 15;

    const float lam = g_lam;
    const float* p1 = O1 + (size_t)r * HD_;
    const float* p2 = O2 + (size_t)r * HD_;

    float a0 = p1[lane]      - lam * p2[lane];
    float a1 = p1[lane + 32] - lam * p2[lane + 32];

    float ss = a0 * a0 + a1 * a1;
#pragma unroll
    for (int off = 16; off > 0; off >>= 1) ss += __shfl_xor_sync(0xffffffffu, ss, off);

    const float inv = rsqrtf(ss * (1.f / 64.f) + 1e-6f);
    const float w0 = normw[h * HD_ + lane];
    const float w1 = normw[h * HD_ + lane + 32];
    const float scale = 1.0f - 0.8f;

    float v0 = a0 * inv * w0 * scale;
    float v1 = a1 * inv * w1 * scale;

    const size_t xb = (size_t)b * S_ * E_;
    const int shi = s >> 10, slo = s & 1023;
    X2[xb + (size_t)(lane * 32 + h * 2 + shi) * E_ + slo] = v0;
    X2[xb + (size_t)((lane + 32) * 32 + h * 2 + shi) * E_ + slo] = v1;
}

// ---------------------------------------------------------------------------
// Launch
// ---------------------------------------------------------------------------
extern "C" void kernel_launch(void* const* d_in, const int* in_sizes, int n_in,
                              void* d_out, int out_size)
{
    const float* x     = (const float*)d_in[0];
    const float* w_qkv = (const float*)d_in[1];
    const float* wo    = (const float*)d_in[2];
    const float* lq1   = (const float*)d_in[3];
    const float* lq2   = (const float*)d_in[4];
    const float* lk1   = (const float*)d_in[5];
    const float* lk2   = (const float*)d_in[6];
    const float* normw = (const float*)d_in[7];
    float* out = (float*)d_out;

    float *p_qkv, *p_O1, *p_O2, *p_X2;
    cudaGetSymbolAddress((void**)&p_qkv, g_qkv);
    cudaGetSymbolAddress((void**)&p_O1, g_O1);
    cudaGetSymbolAddress((void**)&p_O2, g_O2);
    cudaGetSymbolAddress((void**)&p_X2, g_X2);

    // 1) QKV projection: [4096,1024] @ [1024,3072]
    sgemm_kernel<<<dim3(QKV_N / 128, M_TOK / 128), 256>>>(x, w_qkv, p_qkv, M_TOK, QKV_N, E_);

    // 2) lambda scalar
    lambda_kernel<<<1, 32>>>(lq1, lq2, lk1, lk2);

    // 3) two attention halves
    attn_kernel<<<dim3(S_ / 128, B_ * H_), 128>>>(p_qkv, p_O1, 0);
    attn_kernel<<<dim3(S_ / 128, B_ * H_), 128>>>(p_qkv, p_O2, 32);

    // 4) combine + RMSNorm + scrambled reshape
    combine_kernel<<<(B_ * H_ * S_) / 8, 256>>>(p_O1, p_O2, normw, p_X2);

    // 5) output projection: [4096,1024] @ [1024,1024] -> d_out
    sgemm_kernel<<<dim3(E_ / 128, M_TOK / 128), 256>>>(p_X2, wo, out, M_TOK, E_, E_);
}

// round 2
// speedup vs baseline: 1.2909x; 1.2909x over previous
#include <cuda_runtime.h>
#include <cuda_bf16.h>
#include <math.h>

// Problem constants
#define B_  2
#define S_  2048
#define E_  1024
#define H_  16
#define HD_ 64
#define M_TOK (B_ * S_)          // 4096
#define QKV_N (3 * E_)           // 3072

// ---------------------------------------------------------------------------
// Scratch (no allocation allowed -> __device__ globals)
// ---------------------------------------------------------------------------
__device__ float g_qkv[M_TOK * QKV_N];            // [4096, 3072]
__device__ float g_O1[B_ * H_ * S_ * HD_];        // [b,h,s,d]
__device__ float g_O2[B_ * H_ * S_ * HD_];
__device__ float g_X2[B_ * S_ * E_];              // scrambled layout, pre-wo
__device__ float g_lam;

// ---------------------------------------------------------------------------
// SGEMM: C[M,N] = A[M,K] @ B[K,N], row-major, fp32.
// 128x128 block tile, BK=8, 256 threads, 8x8 per thread. (unchanged)
// ---------------------------------------------------------------------------
__global__ __launch_bounds__(256) void sgemm_kernel(
    const float* __restrict__ A, const float* __restrict__ Bm,
    float* __restrict__ C, int M, int N, int K)
{
    __shared__ float As[8][128];
    __shared__ float Bs[8][128];

    const int tid = threadIdx.x;
    const int bm = blockIdx.y * 128;
    const int bn = blockIdx.x * 128;

    const int aRow = tid >> 1;
    const int aCol = (tid & 1) << 2;
    const int bRow = tid >> 5;
    const int bCol = (tid & 31) << 2;

    const float* Aptr = A + (size_t)(bm + aRow) * K + aCol;
    const float* Bptr = Bm + (size_t)bRow * N + bn + bCol;

    const int tr = ((tid >> 4)) << 3;
    const int tc = (tid & 15) << 3;

    float acc[8][8];
#pragma unroll
    for (int i = 0; i < 8; i++)
#pragma unroll
        for (int j = 0; j < 8; j++) acc[i][j] = 0.f;

    for (int k0 = 0; k0 < K; k0 += 8) {
        float4 av = *(const float4*)(Aptr + k0);
        As[aCol + 0][aRow] = av.x;
        As[aCol + 1][aRow] = av.y;
        As[aCol + 2][aRow] = av.z;
        As[aCol + 3][aRow] = av.w;
        *(float4*)(&Bs[bRow][bCol]) = *(const float4*)(Bptr + (size_t)k0 * N);
        __syncthreads();

#pragma unroll
        for (int kk = 0; kk < 8; kk++) {
            float ra[8], rb[8];
#pragma unroll
            for (int i = 0; i < 8; i++) ra[i] = As[kk][tr + i];
#pragma unroll
            for (int j = 0; j < 8; j++) rb[j] = Bs[kk][tc + j];
#pragma unroll
            for (int i = 0; i < 8; i++)
#pragma unroll
                for (int j = 0; j < 8; j++) acc[i][j] += ra[i] * rb[j];
        }
        __syncthreads();
    }

#pragma unroll
    for (int i = 0; i < 8; i++) {
        float* Crow = C + (size_t)(bm + tr + i) * N + bn + tc;
        *(float4*)(Crow)     = make_float4(acc[i][0], acc[i][1], acc[i][2], acc[i][3]);
        *(float4*)(Crow + 4) = make_float4(acc[i][4], acc[i][5], acc[i][6], acc[i][7]);
    }
}

// ---------------------------------------------------------------------------
// Lambda scalar
// ---------------------------------------------------------------------------
__global__ void lambda_kernel(const float* __restrict__ lq1, const float* __restrict__ lq2,
                              const float* __restrict__ lk1, const float* __restrict__ lk2)
{
    if (threadIdx.x == 0) {
        float d1 = 0.f, d2 = 0.f;
        for (int i = 0; i < HD_; i++) { d1 += lq1[i] * lk1[i]; d2 += lq2[i] * lk2[i]; }
        g_lam = expf(d1) - expf(d2) + 0.8f;
    }
}

// ---------------------------------------------------------------------------
// Flash attention, both halves via blockIdx.z (0 -> O1/d0=0, 1 -> O2/d0=32).
// float4 SMEM layout: every LDS.128 feeds 4 FMAs. launch_bounds(128,3)
// caps regs at ~170 so 3 CTAs/SM (12 warps) are resident.
// grid = (S/128, B*H, 2), block = 128.
// ---------------------------------------------------------------------------
__global__ void __launch_bounds__(128, 3) attn_kernel(
    const float* __restrict__ qkv, float* __restrict__ O1, float* __restrict__ O2)
{
    __shared__ float4 Ks[64][8];    // [key][d/4], half head (32 floats)
    __shared__ float4 Vs[64][16];   // [key][d/4], full head (64 floats)

    const int half = blockIdx.z;
    const int d0 = half << 5;
    const int bh = blockIdx.y;
    const int b = bh >> 4, h = bh & 15;
    const int tid = threadIdx.x;
    const int qs = blockIdx.x * 128 + tid;
    const float* base = qkv + (size_t)b * S_ * QKV_N;

    // q scaled by 1/sqrt(64) * log2(e) (softmax in base 2)
    float4 q4[8];
    {
        const float* qp = base + (size_t)qs * QKV_N + h * HD_ + d0;
        const float sc = 0.125f * 1.4426950408889634f;
#pragma unroll
        for (int i = 0; i < 8; i++) {
            float4 v = *(const float4*)(qp + 4 * i);
            q4[i] = make_float4(v.x * sc, v.y * sc, v.z * sc, v.w * sc);
        }
    }

    float m = -1e30f, l = 0.f;
    float4 o4[16];
#pragma unroll
    for (int d = 0; d < 16; d++) o4[d] = make_float4(0.f, 0.f, 0.f, 0.f);

    const int koff = E_ + h * HD_ + d0;
    const int voff = 2 * E_ + h * HD_;

    for (int t0 = 0; t0 < S_; t0 += 64) {
        __syncthreads();
#pragma unroll
        for (int it = 0; it < 4; it++) {           // K tile: 64 keys x 8 float4
            int f = tid + it * 128;
            int j = f >> 3, dc = f & 7;
            Ks[j][dc] = *(const float4*)(base + (size_t)(t0 + j) * QKV_N + koff + 4 * dc);
        }
#pragma unroll
        for (int it = 0; it < 8; it++) {           // V tile: 64 keys x 16 float4
            int f = tid + it * 128;
            int j = f >> 4, dc = f & 15;
            Vs[j][dc] = *(const float4*)(base + (size_t)(t0 + j) * QKV_N + voff + 4 * dc);
        }
        __syncthreads();

#pragma unroll 1
        for (int c0 = 0; c0 < 64; c0 += 16) {
            float s[16];
#pragma unroll
            for (int j = 0; j < 16; j++) {
                float4 a0 = make_float4(0.f, 0.f, 0.f, 0.f);
                float4 a1 = make_float4(0.f, 0.f, 0.f, 0.f);
#pragma unroll
                for (int dq = 0; dq < 8; dq += 2) {
                    float4 k0v = Ks[c0 + j][dq];
                    float4 k1v = Ks[c0 + j][dq + 1];
                    a0.x = fmaf(q4[dq].x, k0v.x, a0.x);
                    a0.y = fmaf(q4[dq].y, k0v.y, a0.y);
                    a0.z = fmaf(q4[dq].z, k0v.z, a0.z);
                    a0.w = fmaf(q4[dq].w, k0v.w, a0.w);
                    a1.x = fmaf(q4[dq + 1].x, k1v.x, a1.x);
                    a1.y = fmaf(q4[dq + 1].y, k1v.y, a1.y);
                    a1.z = fmaf(q4[dq + 1].z, k1v.z, a1.z);
                    a1.w = fmaf(q4[dq + 1].w, k1v.w, a1.w);
                }
                s[j] = (a0.x + a0.y) + (a0.z + a0.w) + ((a1.x + a1.y) + (a1.z + a1.w));
            }
            float tm = s[0];
#pragma unroll
            for (int j = 1; j < 16; j++) tm = fmaxf(tm, s[j]);
            float mn = fmaxf(m, tm);
            float corr = exp2f(m - mn);
            l *= corr;
#pragma unroll
            for (int d = 0; d < 16; d++) {
                o4[d].x *= corr; o4[d].y *= corr; o4[d].z *= corr; o4[d].w *= corr;
            }
#pragma unroll
            for (int j = 0; j < 16; j++) {
                float p = exp2f(s[j] - mn);
                l += p;
#pragma unroll
                for (int d = 0; d < 16; d++) {
                    float4 v = Vs[c0 + j][d];
                    o4[d].x = fmaf(p, v.x, o4[d].x);
                    o4[d].y = fmaf(p, v.y, o4[d].y);
                    o4[d].z = fmaf(p, v.z, o4[d].z);
                    o4[d].w = fmaf(p, v.w, o4[d].w);
                }
            }
            m = mn;
        }
    }

    const float inv = 1.f / l;
    float* op = (half ? O2 : O1) + ((size_t)bh * S_ + qs) * HD_;
#pragma unroll
    for (int d = 0; d < 16; d++)
        *(float4*)(op + 4 * d) = make_float4(o4[d].x * inv, o4[d].y * inv,
                                             o4[d].z * inv, o4[d].w * inv);
}

// ---------------------------------------------------------------------------
// Combine: out = O1 - lam*O2, per-head RMSNorm, *norm_w*(1-0.8),
// scatter into the reference's scrambled layout:
//   X2[b][d*32 + h*2 + (s>>10)][s & 1023]
// ---------------------------------------------------------------------------
__global__ __launch_bounds__(256) void combine_kernel(
    const float* __restrict__ O1, const float* __restrict__ O2,
    const float* __restrict__ normw, float* __restrict__ X2)
{
    const int r = blockIdx.x * 8 + (threadIdx.x >> 5);   // row in [0, B*H*S)
    const int lane = threadIdx.x & 31;
    const int bh = r >> 11;
    const int s = r & 2047;
    const int b = bh >> 4, h = bh & 15;

    const float lam = g_lam;
    const float* p1 = O1 + (size_t)r * HD_;
    const float* p2 = O2 + (size_t)r * HD_;

    float a0 = p1[lane]      - lam * p2[lane];
    float a1 = p1[lane + 32] - lam * p2[lane + 32];

    float ss = a0 * a0 + a1 * a1;
#pragma unroll
    for (int off = 16; off > 0; off >>= 1) ss += __shfl_xor_sync(0xffffffffu, ss, off);

    const float inv = rsqrtf(ss * (1.f / 64.f) + 1e-6f);
    const float w0 = normw[h * HD_ + lane];
    const float w1 = normw[h * HD_ + lane + 32];
    const float scale = 1.0f - 0.8f;

    float v0 = a0 * inv * w0 * scale;
    float v1 = a1 * inv * w1 * scale;

    const size_t xb = (size_t)b * S_ * E_;
    const int shi = s >> 10, slo = s & 1023;
    X2[xb + (size_t)(lane * 32 + h * 2 + shi) * E_ + slo] = v0;
    X2[xb + (size_t)((lane + 32) * 32 + h * 2 + shi) * E_ + slo] = v1;
}

// ---------------------------------------------------------------------------
// Launch
// ---------------------------------------------------------------------------
extern "C" void kernel_launch(void* const* d_in, const int* in_sizes, int n_in,
                              void* d_out, int out_size)
{
    const float* x     = (const float*)d_in[0];
    const float* w_qkv = (const float*)d_in[1];
    const float* wo    = (const float*)d_in[2];
    const float* lq1   = (const float*)d_in[3];
    const float* lq2   = (const float*)d_in[4];
    const float* lk1   = (const float*)d_in[5];
    const float* lk2   = (const float*)d_in[6];
    const float* normw = (const float*)d_in[7];
    float* out = (float*)d_out;

    float *p_qkv, *p_O1, *p_O2, *p_X2;
    cudaGetSymbolAddress((void**)&p_qkv, g_qkv);
    cudaGetSymbolAddress((void**)&p_O1, g_O1);
    cudaGetSymbolAddress((void**)&p_O2, g_O2);
    cudaGetSymbolAddress((void**)&p_X2, g_X2);

    // 1) QKV projection: [4096,1024] @ [1024,3072]
    sgemm_kernel<<<dim3(QKV_N / 128, M_TOK / 128), 256>>>(x, w_qkv, p_qkv, M_TOK, QKV_N, E_);

    // 2) lambda scalar
    lambda_kernel<<<1, 32>>>(lq1, lq2, lk1, lk2);

    // 3) both attention halves in one launch (z = half)
    attn_kernel<<<dim3(S_ / 128, B_ * H_, 2), 128>>>(p_qkv, p_O1, p_O2);

    // 4) combine + RMSNorm + scrambled reshape
    combine_kernel<<<(B_ * H_ * S_) / 8, 256>>>(p_O1, p_O2, normw, p_X2);

    // 5) output projection: [4096,1024] @ [1024,1024] -> d_out
    sgemm_kernel<<<dim3(E_ / 128, M_TOK / 128), 256>>>(p_X2, wo, out, M_TOK, E_, E_);
}

// round 4
// speedup vs baseline: 1.6287x; 1.2617x over previous
#include <cuda_runtime.h>
#include <cuda_bf16.h>
#include <math.h>
#include <stdint.h>

// Problem constants
#define B_  2
#define S_  2048
#define E_  1024
#define H_  16
#define HD_ 64
#define M_TOK (B_ * S_)          // 4096
#define QKV_N (3 * E_)           // 3072

// ---------------------------------------------------------------------------
// Scratch (no allocation allowed -> __device__ globals)
// ---------------------------------------------------------------------------
__device__ float g_qkv[M_TOK * QKV_N];            // [4096, 3072] fp32
__device__ float g_O1[B_ * H_ * S_ * HD_];
__device__ float g_O2[B_ * H_ * S_ * HD_];
__device__ float g_lam;
__device__ __nv_bfloat16 g_xh[M_TOK * E_];        // x split hi/lo [4096,1024]
__device__ __nv_bfloat16 g_xl[M_TOK * E_];
__device__ __nv_bfloat16 g_X2h[M_TOK * E_];       // scrambled pre-wo, hi/lo
__device__ __nv_bfloat16 g_X2l[M_TOK * E_];
__device__ __nv_bfloat16 g_wqkvT_hi[QKV_N * E_];  // [3072,1024] K-major
__device__ __nv_bfloat16 g_wqkvT_lo[QKV_N * E_];
__device__ __nv_bfloat16 g_woT_hi[E_ * E_];       // [1024,1024] K-major
__device__ __nv_bfloat16 g_woT_lo[E_ * E_];

// ---------------------------------------------------------------------------
// Helpers
// ---------------------------------------------------------------------------
__device__ __forceinline__ uint32_t smem_to_u32(const void* p) {
    uint32_t a;
    asm("{ .reg .u64 tmp; cvta.to.shared.u64 tmp, %1; cvt.u32.u64 %0, tmp; }"
        : "=r"(a) : "l"(p));
    return a;
}
#define CP16(daddr, gptr) \
    asm volatile("cp.async.cg.shared.global [%0], [%1], 16;" \
                 :: "r"(daddr), "l"(gptr))
#define CP_COMMIT() asm volatile("cp.async.commit_group;")
#define LDSM4(r, addr) \
    asm volatile("ldmatrix.sync.aligned.m8n8.x4.shared.b16 {%0,%1,%2,%3}, [%4];" \
                 : "=r"((r)[0]), "=r"((r)[1]), "=r"((r)[2]), "=r"((r)[3]) \
                 : "r"(addr))
#define MMA16816(d, a, b0_, b1_) \
    asm volatile("mma.sync.aligned.m16n8k16.row.col.f32.bf16.bf16.f32 " \
                 "{%0,%1,%2,%3}, {%4,%5,%6,%7}, {%8,%9}, {%0,%1,%2,%3};" \
                 : "+f"((d)[0]), "+f"((d)[1]), "+f"((d)[2]), "+f"((d)[3]) \
                 : "r"((a)[0]), "r"((a)[1]), "r"((a)[2]), "r"((a)[3]), \
                   "r"(b0_), "r"(b1_))

__device__ __forceinline__ void bf16_split(float v, __nv_bfloat16& h, __nv_bfloat16& l) {
    h = __float2bfloat16(v);
    l = __float2bfloat16(v - __bfloat162float(h));
}

// ---------------------------------------------------------------------------
// Weight transpose + bf16 hi/lo split:  in [K,N] fp32  ->  out [N,K] bf16 x2
// ---------------------------------------------------------------------------
__global__ __launch_bounds__(256) void transpose_split(
    const float* __restrict__ in, __nv_bfloat16* __restrict__ oh,
    __nv_bfloat16* __restrict__ ol, int K, int N)
{
    __shared__ float t[32][33];
    const int tx = threadIdx.x & 31, ty = threadIdx.x >> 5;
    const int n0 = blockIdx.x * 32, k0 = blockIdx.y * 32;
#pragma unroll
    for (int j = 0; j < 32; j += 8)
        t[ty + j][tx] = in[(size_t)(k0 + ty + j) * N + n0 + tx];
    __syncthreads();
#pragma unroll
    for (int j = 0; j < 32; j += 8) {
        float v = t[tx][ty + j];
        __nv_bfloat16 h, l; bf16_split(v, h, l);
        size_t o = (size_t)(n0 + ty + j) * K + k0 + tx;
        oh[o] = h; ol[o] = l;
    }
}

// ---------------------------------------------------------------------------
// Elementwise fp32 -> bf16 hi/lo split (for x)
// ---------------------------------------------------------------------------
__global__ __launch_bounds__(256) void split_kernel(
    const float* __restrict__ in, __nv_bfloat16* __restrict__ oh,
    __nv_bfloat16* __restrict__ ol)
{
    int i = (blockIdx.x * 256 + threadIdx.x) * 4;
    float4 v = *(const float4*)(in + i);
    __nv_bfloat16 h0, h1, h2, h3, l0, l1, l2, l3;
    bf16_split(v.x, h0, l0); bf16_split(v.y, h1, l1);
    bf16_split(v.z, h2, l2); bf16_split(v.w, h3, l3);
    __nv_bfloat162* ph = (__nv_bfloat162*)(oh + i);
    __nv_bfloat162* pl = (__nv_bfloat162*)(ol + i);
    ph[0] = __nv_bfloat162(h0, h1); ph[1] = __nv_bfloat162(h2, h3);
    pl[0] = __nv_bfloat162(l0, l1); pl[1] = __nv_bfloat162(l2, l3);
}

// ---------------------------------------------------------------------------
// Tensor-core GEMM via mma.sync (bf16 split): C[M,N] fp32 = (Ah+Al)@(Bh+Bl)^T
// A: [M,K] bf16 hi/lo row-major; B: [N,K] bf16 hi/lo (K-major).
// 128x128 tile, BK=32, 256 thr (8 warps, warp tile 32x64), 2-stage cp.async.
// ---------------------------------------------------------------------------
#define PITCH 40                       // bf16 per smem row (80B, conflict-free)
#define BUFB  (128 * PITCH * 2)        // 10240 B per operand buffer
#define STAGEB (4 * BUFB)              // 40960 B per stage
#define GEMM_SMEM (2 * STAGEB)         // 81920 B

__global__ void __launch_bounds__(256, 2) mma_gemm(
    const __nv_bfloat16* __restrict__ Ah, const __nv_bfloat16* __restrict__ Al,
    const __nv_bfloat16* __restrict__ Bh, const __nv_bfloat16* __restrict__ Bl,
    float* __restrict__ C, int M, int N, int K)
{
    extern __shared__ __align__(16) uint8_t smem[];
    const uint32_t sbase = smem_to_u32(smem);
    const int tid = threadIdx.x, lane = tid & 31, wid = tid >> 5;
    const int wr = wid & 3, wc = wid >> 2;         // warp grid 4(m) x 2(n)
    const int bm = blockIdx.y * 128, bn = blockIdx.x * 128;
    const int NK = K / 32;

    float acc[2][8][4];
#pragma unroll
    for (int i = 0; i < 2; i++)
#pragma unroll
        for (int j = 0; j < 8; j++)
#pragma unroll
            for (int r = 0; r < 4; r++) acc[i][j][r] = 0.f;

    // ---- stage issue: 2 chunks/thread/buffer, 4 buffers ----
#define ISSUE(kt, stg) do {                                                    \
        uint32_t sb_ = sbase + (stg) * STAGEB;                                 \
        _Pragma("unroll")                                                      \
        for (int hf = 0; hf < 2; hf++) {                                       \
            int c = tid + hf * 256;                                            \
            int row = c >> 2, colc = (c & 3) * 8;                              \
            uint32_t doff = (uint32_t)(row * (PITCH * 2) + colc * 2);          \
            size_t ga = (size_t)(bm + row) * K + (kt) * 32 + colc;             \
            size_t gb = (size_t)(bn + row) * K + (kt) * 32 + colc;             \
            CP16(sb_ + 0 * BUFB + doff, Ah + ga);                              \
            CP16(sb_ + 1 * BUFB + doff, Al + ga);                              \
            CP16(sb_ + 2 * BUFB + doff, Bh + gb);                              \
            CP16(sb_ + 3 * BUFB + doff, Bl + gb);                              \
        }                                                                      \
        CP_COMMIT();                                                           \
    } while (0)

    ISSUE(0, 0);

    for (int kt = 0; kt < NK; kt++) {
        const int cur = kt & 1;
        if (kt + 1 < NK) {
            ISSUE(kt + 1, (kt + 1) & 1);
            asm volatile("cp.async.wait_group 1;");
        } else {
            asm volatile("cp.async.wait_group 0;");
        }
        __syncthreads();

        const uint32_t sA_h = sbase + cur * STAGEB;
        const uint32_t sA_l = sA_h + BUFB;
        const uint32_t sB_h = sA_h + 2 * BUFB;
        const uint32_t sB_l = sA_h + 3 * BUFB;

#pragma unroll
        for (int ks = 0; ks < 2; ks++) {
            uint32_t ah[2][4], al[2][4];
#pragma unroll
            for (int i = 0; i < 2; i++) {
                uint32_t ra = (uint32_t)((wr * 32 + i * 16 + (lane & 15)) * (PITCH * 2)
                              + (ks * 16 + ((lane >> 4) << 3)) * 2);
                LDSM4(ah[i], sA_h + ra);
                LDSM4(al[i], sA_l + ra);
            }
#pragma unroll
            for (int jp = 0; jp < 4; jp++) {
                uint32_t rowb = (uint32_t)(wc * 64 + jp * 16 + ((lane >> 4) << 3) + (lane & 7));
                uint32_t colb = (uint32_t)(ks * 16 + (((lane >> 3) & 1) << 3));
                uint32_t rb = rowb * (PITCH * 2) + colb * 2;
                uint32_t bh[4], bl[4];
                LDSM4(bh, sB_h + rb);
                LDSM4(bl, sB_l + rb);
#pragma unroll
                for (int i = 0; i < 2; i++) {
                    MMA16816(acc[i][jp * 2],     ah[i], bh[0], bh[1]);
                    MMA16816(acc[i][jp * 2],     al[i], bh[0], bh[1]);
                    MMA16816(acc[i][jp * 2],     ah[i], bl[0], bl[1]);
                    MMA16816(acc[i][jp * 2 + 1], ah[i], bh[2], bh[3]);
                    MMA16816(acc[i][jp * 2 + 1], al[i], bh[2], bh[3]);
                    MMA16816(acc[i][jp * 2 + 1], ah[i], bl[2], bl[3]);
                }
            }
        }
        __syncthreads();
    }

    // ---- epilogue ----
#pragma unroll
    for (int i = 0; i < 2; i++) {
        int mrow = bm + wr * 32 + i * 16 + (lane >> 2);
#pragma unroll
        for (int j = 0; j < 8; j++) {
            int ncol = bn + wc * 64 + j * 8 + (lane & 3) * 2;
            *(float2*)(C + (size_t)mrow * N + ncol) =
                make_float2(acc[i][j][0], acc[i][j][1]);
            *(float2*)(C + (size_t)(mrow + 8) * N + ncol) =
                make_float2(acc[i][j][2], acc[i][j][3]);
        }
    }
#undef ISSUE
}

// ---------------------------------------------------------------------------
// Lambda scalar
// ---------------------------------------------------------------------------
__global__ void lambda_kernel(const float* __restrict__ lq1, const float* __restrict__ lq2,
                              const float* __restrict__ lk1, const float* __restrict__ lk2)
{
    if (threadIdx.x == 0) {
        float d1 = 0.f, d2 = 0.f;
        for (int i = 0; i < HD_; i++) { d1 += lq1[i] * lk1[i]; d2 += lq2[i] * lk2[i]; }
        g_lam = expf(d1) - expf(d2) + 0.8f;
    }
}

// ---------------------------------------------------------------------------
// Flash attention (unchanged from R2): both halves via blockIdx.z.
// ---------------------------------------------------------------------------
__global__ void __launch_bounds__(128, 3) attn_kernel(
    const float* __restrict__ qkv, float* __restrict__ O1, float* __restrict__ O2)
{
    __shared__ float4 Ks[64][8];
    __shared__ float4 Vs[64][16];

    const int half = blockIdx.z;
    const int d0 = half << 5;
    const int bh = blockIdx.y;
    const int b = bh >> 4, h = bh & 15;
    const int tid = threadIdx.x;
    const int qs = blockIdx.x * 128 + tid;
    const float* base = qkv + (size_t)b * S_ * QKV_N;

    float4 q4[8];
    {
        const float* qp = base + (size_t)qs * QKV_N + h * HD_ + d0;
        const float sc = 0.125f * 1.4426950408889634f;
#pragma unroll
        for (int i = 0; i < 8; i++) {
            float4 v = *(const float4*)(qp + 4 * i);
            q4[i] = make_float4(v.x * sc, v.y * sc, v.z * sc, v.w * sc);
        }
    }

    float m = -1e30f, l = 0.f;
    float4 o4[16];
#pragma unroll
    for (int d = 0; d < 16; d++) o4[d] = make_float4(0.f, 0.f, 0.f, 0.f);

    const int koff = E_ + h * HD_ + d0;
    const int voff = 2 * E_ + h * HD_;

    for (int t0 = 0; t0 < S_; t0 += 64) {
        __syncthreads();
#pragma unroll
        for (int it = 0; it < 4; it++) {
            int f = tid + it * 128;
            int j = f >> 3, dc = f & 7;
            Ks[j][dc] = *(const float4*)(base + (size_t)(t0 + j) * QKV_N + koff + 4 * dc);
        }
#pragma unroll
        for (int it = 0; it < 8; it++) {
            int f = tid + it * 128;
            int j = f >> 4, dc = f & 15;
            Vs[j][dc] = *(const float4*)(base + (size_t)(t0 + j) * QKV_N + voff + 4 * dc);
        }
        __syncthreads();

#pragma unroll 1
        for (int c0 = 0; c0 < 64; c0 += 16) {
            float s[16];
#pragma unroll
            for (int j = 0; j < 16; j++) {
                float4 a0 = make_float4(0.f, 0.f, 0.f, 0.f);
                float4 a1 = make_float4(0.f, 0.f, 0.f, 0.f);
#pragma unroll
                for (int dq = 0; dq < 8; dq += 2) {
                    float4 k0v = Ks[c0 + j][dq];
                    float4 k1v = Ks[c0 + j][dq + 1];
                    a0.x = fmaf(q4[dq].x, k0v.x, a0.x);
                    a0.y = fmaf(q4[dq].y, k0v.y, a0.y);
                    a0.z = fmaf(q4[dq].z, k0v.z, a0.z);
                    a0.w = fmaf(q4[dq].w, k0v.w, a0.w);
                    a1.x = fmaf(q4[dq + 1].x, k1v.x, a1.x);
                    a1.y = fmaf(q4[dq + 1].y, k1v.y, a1.y);
                    a1.z = fmaf(q4[dq + 1].z, k1v.z, a1.z);
                    a1.w = fmaf(q4[dq + 1].w, k1v.w, a1.w);
                }
                s[j] = (a0.x + a0.y) + (a0.z + a0.w) + ((a1.x + a1.y) + (a1.z + a1.w));
            }
            float tm = s[0];
#pragma unroll
            for (int j = 1; j < 16; j++) tm = fmaxf(tm, s[j]);
            float mn = fmaxf(m, tm);
            float corr = exp2f(m - mn);
            l *= corr;
#pragma unroll
            for (int d = 0; d < 16; d++) {
                o4[d].x *= corr; o4[d].y *= corr; o4[d].z *= corr; o4[d].w *= corr;
            }
#pragma unroll
            for (int j = 0; j < 16; j++) {
                float p = exp2f(s[j] - mn);
                l += p;
#pragma unroll
                for (int d = 0; d < 16; d++) {
                    float4 v = Vs[c0 + j][d];
                    o4[d].x = fmaf(p, v.x, o4[d].x);
                    o4[d].y = fmaf(p, v.y, o4[d].y);
                    o4[d].z = fmaf(p, v.z, o4[d].z);
                    o4[d].w = fmaf(p, v.w, o4[d].w);
                }
            }
            m = mn;
        }
    }

    const float inv = 1.f / l;
    float* op = (half ? O2 : O1) + ((size_t)bh * S_ + qs) * HD_;
#pragma unroll
    for (int d = 0; d < 16; d++)
        *(float4*)(op + 4 * d) = make_float4(o4[d].x * inv, o4[d].y * inv,
                                             o4[d].z * inv, o4[d].w * inv);
}

// ---------------------------------------------------------------------------
// Combine: out = O1 - lam*O2, per-head RMSNorm, *norm_w*(1-0.8),
// scatter into scrambled layout as bf16 hi/lo (fused split for GEMM2).
//   X2[b][d*32 + h*2 + (s>>10)][s & 1023]
// ---------------------------------------------------------------------------
__global__ __launch_bounds__(256) void combine_kernel(
    const float* __restrict__ O1, const float* __restrict__ O2,
    const float* __restrict__ normw,
    __nv_bfloat16* __restrict__ X2h, __nv_bfloat16* __restrict__ X2l)
{
    const int r = blockIdx.x * 8 + (threadIdx.x >> 5);
    const int lane = threadIdx.x & 31;
    const int bh = r >> 11;
    const int s = r & 2047;
    const int b = bh >> 4, h = bh & 15;

    const float lam = g_lam;
    const float* p1 = O1 + (size_t)r * HD_;
    const float* p2 = O2 + (size_t)r * HD_;

    float a0 = p1[lane]      - lam * p2[lane];
    float a1 = p1[lane + 32] - lam * p2[lane + 32];

    float ss = a0 * a0 + a1 * a1;
#pragma unroll
    for (int off = 16; off > 0; off >>= 1) ss += __shfl_xor_sync(0xffffffffu, ss, off);

    const float inv = rsqrtf(ss * (1.f / 64.f) + 1e-6f);
    const float w0 = normw[h * HD_ + lane];
    const float w1 = normw[h * HD_ + lane + 32];
    const float scale = 1.0f - 0.8f;

    float v0 = a0 * inv * w0 * scale;
    float v1 = a1 * inv * w1 * scale;

    const size_t xb = (size_t)b * S_ * E_;
    const int shi = s >> 10, slo = s & 1023;
    size_t i0 = xb + (size_t)(lane * 32 + h * 2 + shi) * E_ + slo;
    size_t i1 = xb + (size_t)((lane + 32) * 32 + h * 2 + shi) * E_ + slo;

    __nv_bfloat16 h0, h1, l0, l1;
    bf16_split(v0, h0, l0);
    bf16_split(v1, h1, l1);
    X2h[i0] = h0; X2l[i0] = l0;
    X2h[i1] = h1; X2l[i1] = l1;
}

// ---------------------------------------------------------------------------
// Launch
// ---------------------------------------------------------------------------
extern "C" void kernel_launch(void* const* d_in, const int* in_sizes, int n_in,
                              void* d_out, int out_size)
{
    const float* x     = (const float*)d_in[0];
    const float* w_qkv = (const float*)d_in[1];
    const float* wo    = (const float*)d_in[2];
    const float* lq1   = (const float*)d_in[3];
    const float* lq2   = (const float*)d_in[4];
    const float* lk1   = (const float*)d_in[5];
    const float* lk2   = (const float*)d_in[6];
    const float* normw = (const float*)d_in[7];
    float* out = (float*)d_out;

    float *p_qkv, *p_O1, *p_O2;
    cudaGetSymbolAddress((void**)&p_qkv, g_qkv);
    cudaGetSymbolAddress((void**)&p_O1, g_O1);
    cudaGetSymbolAddress((void**)&p_O2, g_O2);
    __nv_bfloat16 *p_xh, *p_xl, *p_X2h, *p_X2l, *p_wqh, *p_wql, *p_woh, *p_wol;
    cudaGetSymbolAddress((void**)&p_xh, g_xh);
    cudaGetSymbolAddress((void**)&p_xl, g_xl);
    cudaGetSymbolAddress((void**)&p_X2h, g_X2h);
    cudaGetSymbolAddress((void**)&p_X2l, g_X2l);
    cudaGetSymbolAddress((void**)&p_wqh, g_wqkvT_hi);
    cudaGetSymbolAddress((void**)&p_wql, g_wqkvT_lo);
    cudaGetSymbolAddress((void**)&p_woh, g_woT_hi);
    cudaGetSymbolAddress((void**)&p_wol, g_woT_lo);

    cudaFuncSetAttribute(mma_gemm, cudaFuncAttributeMaxDynamicSharedMemorySize,
                         GEMM_SMEM);

    // 0) splits: x -> bf16 hi/lo; weights -> transposed bf16 hi/lo
    split_kernel<<<(M_TOK * E_) / (256 * 4), 256>>>(x, p_xh, p_xl);
    transpose_split<<<dim3(QKV_N / 32, E_ / 32), 256>>>(w_qkv, p_wqh, p_wql, E_, QKV_N);
    transpose_split<<<dim3(E_ / 32, E_ / 32), 256>>>(wo, p_woh, p_wol, E_, E_);

    // 1) QKV projection (tensor cores): [4096,1024] @ [1024,3072]
    mma_gemm<<<dim3(QKV_N / 128, M_TOK / 128), 256, GEMM_SMEM>>>(
        p_xh, p_xl, p_wqh, p_wql, p_qkv, M_TOK, QKV_N, E_);

    // 2) lambda scalar
    lambda_kernel<<<1, 32>>>(lq1, lq2, lk1, lk2);

    // 3) both attention halves
    attn_kernel<<<dim3(S_ / 128, B_ * H_, 2), 128>>>(p_qkv, p_O1, p_O2);

    // 4) combine + RMSNorm + scrambled reshape (emits bf16 hi/lo)
    combine_kernel<<<(B_ * H_ * S_) / 8, 256>>>(p_O1, p_O2, normw, p_X2h, p_X2l);

    // 5) output projection (tensor cores): [4096,1024] @ [1024,1024] -> d_out
    mma_gemm<<<dim3(E_ / 128, M_TOK / 128), 256, GEMM_SMEM>>>(
        p_X2h, p_X2l, p_woh, p_wol, out, M_TOK, E_, E_);
}

// round 6
// speedup vs baseline: 4.0536x; 2.4888x over previous
#include <cuda_runtime.h>
#include <cuda_bf16.h>
#include <math.h>
#include <stdint.h>

// Problem constants
#define B_  2
#define S_  2048
#define E_  1024
#define H_  16
#define HD_ 64
#define M_TOK (B_ * S_)          // 4096
#define QKV_N (3 * E_)           // 3072

// ---------------------------------------------------------------------------
// Scratch (no allocation allowed -> __device__ globals)
// ---------------------------------------------------------------------------
__device__ float g_O1[B_ * H_ * S_ * HD_];
__device__ float g_O2[B_ * H_ * S_ * HD_];
__device__ float g_lam;
__device__ __nv_bfloat16 g_xh[M_TOK * E_];        // x split hi/lo
__device__ __nv_bfloat16 g_xl[M_TOK * E_];
__device__ __nv_bfloat16 g_qkvh[M_TOK * QKV_N];   // qkv split hi/lo
__device__ __nv_bfloat16 g_qkvl[M_TOK * QKV_N];
__device__ __nv_bfloat16 g_vth[B_ * H_ * HD_ * S_];  // V^T [b,h,d,s]
__device__ __nv_bfloat16 g_vtl[B_ * H_ * HD_ * S_];
__device__ __nv_bfloat16 g_X2h[M_TOK * E_];       // scrambled pre-wo hi/lo
__device__ __nv_bfloat16 g_X2l[M_TOK * E_];
__device__ __nv_bfloat16 g_wqkvT_hi[QKV_N * E_];
__device__ __nv_bfloat16 g_wqkvT_lo[QKV_N * E_];
__device__ __nv_bfloat16 g_woT_hi[E_ * E_];
__device__ __nv_bfloat16 g_woT_lo[E_ * E_];

// ---------------------------------------------------------------------------
// Helpers
// ---------------------------------------------------------------------------
__device__ __forceinline__ uint32_t smem_to_u32(const void* p) {
    uint32_t a;
    asm("{ .reg .u64 tmp; cvta.to.shared.u64 tmp, %1; cvt.u32.u64 %0, tmp; }"
        : "=r"(a) : "l"(p));
    return a;
}
#define CP16(daddr, gptr) \
    asm volatile("cp.async.cg.shared.global [%0], [%1], 16;" \
                 :: "r"(daddr), "l"(gptr))
#define CP_COMMIT() asm volatile("cp.async.commit_group;")
#define LDSM4(r, addr) \
    asm volatile("ldmatrix.sync.aligned.m8n8.x4.shared.b16 {%0,%1,%2,%3}, [%4];" \
                 : "=r"((r)[0]), "=r"((r)[1]), "=r"((r)[2]), "=r"((r)[3]) \
                 : "r"(addr))
#define MMA16816(d, a, b0_, b1_) \
    asm volatile("mma.sync.aligned.m16n8k16.row.col.f32.bf16.bf16.f32 " \
                 "{%0,%1,%2,%3}, {%4,%5,%6,%7}, {%8,%9}, {%0,%1,%2,%3};" \
                 : "+f"((d)[0]), "+f"((d)[1]), "+f"((d)[2]), "+f"((d)[3]) \
                 : "r"((a)[0]), "r"((a)[1]), "r"((a)[2]), "r"((a)[3]), \
                   "r"(b0_), "r"(b1_))
// pack two fp32 -> bf16x2 (lo = first arg, hi = second)
#define PACKBF(r, lo_, hi_) \
    asm("cvt.rn.bf16x2.f32 %0, %1, %2;" : "=r"(r) : "f"(hi_), "f"(lo_))
#define SMEM_SWIZZLE_128B(byte_offset) \
    ((byte_offset) ^ (((byte_offset) >> 3) & 0x70))

__device__ __forceinline__ void bf16_split(float v, __nv_bfloat16& h, __nv_bfloat16& l) {
    h = __float2bfloat16(v);
    l = __float2bfloat16(v - __bfloat162float(h));
}

// ---------------------------------------------------------------------------
// Weight transpose + bf16 hi/lo split:  in [K,N] fp32  ->  out [N,K] bf16 x2
// ---------------------------------------------------------------------------
__global__ __launch_bounds__(256) void transpose_split(
    const float* __restrict__ in, __nv_bfloat16* __restrict__ oh,
    __nv_bfloat16* __restrict__ ol, int K, int N)
{
    __shared__ float t[32][33];
    const int tx = threadIdx.x & 31, ty = threadIdx.x >> 5;
    const int n0 = blockIdx.x * 32, k0 = blockIdx.y * 32;
#pragma unroll
    for (int j = 0; j < 32; j += 8)
        t[ty + j][tx] = in[(size_t)(k0 + ty + j) * N + n0 + tx];
    __syncthreads();
#pragma unroll
    for (int j = 0; j < 32; j += 8) {
        float v = t[tx][ty + j];
        __nv_bfloat16 h, l; bf16_split(v, h, l);
        size_t o = (size_t)(n0 + ty + j) * K + k0 + tx;
        oh[o] = h; ol[o] = l;
    }
}

// ---------------------------------------------------------------------------
// Elementwise fp32 -> bf16 hi/lo split (for x)
// ---------------------------------------------------------------------------
__global__ __launch_bounds__(256) void split_kernel(
    const float* __restrict__ in, __nv_bfloat16* __restrict__ oh,
    __nv_bfloat16* __restrict__ ol)
{
    int i = (blockIdx.x * 256 + threadIdx.x) * 4;
    float4 v = *(const float4*)(in + i);
    __nv_bfloat16 h0, h1, h2, h3, l0, l1, l2, l3;
    bf16_split(v.x, h0, l0); bf16_split(v.y, h1, l1);
    bf16_split(v.z, h2, l2); bf16_split(v.w, h3, l3);
    __nv_bfloat162* ph = (__nv_bfloat162*)(oh + i);
    __nv_bfloat162* pl = (__nv_bfloat162*)(ol + i);
    ph[0] = __nv_bfloat162(h0, h1); ph[1] = __nv_bfloat162(h2, h3);
    pl[0] = __nv_bfloat162(l0, l1); pl[1] = __nv_bfloat162(l2, l3);
}

// ---------------------------------------------------------------------------
// V transpose (bf16 -> bf16): qkv v-part [b,s,h,d] -> [b,h,d,s], hi & lo
// ---------------------------------------------------------------------------
__global__ __launch_bounds__(256) void vtrans_kernel(
    const __nv_bfloat16* __restrict__ qh, const __nv_bfloat16* __restrict__ ql,
    __nv_bfloat16* __restrict__ vth, __nv_bfloat16* __restrict__ vtl)
{
    __shared__ __nv_bfloat16 th[32][33], tl[32][33];
    const int bh = blockIdx.z, b = bh >> 4, h = bh & 15;
    const int s0 = blockIdx.x * 32, d0 = blockIdx.y * 32;
    const int tx = threadIdx.x & 31, ty = threadIdx.x >> 5;
#pragma unroll
    for (int j = 0; j < 32; j += 8) {
        size_t ga = (size_t)(b * S_ + s0 + ty + j) * QKV_N + 2 * E_ + h * HD_ + d0 + tx;
        th[ty + j][tx] = qh[ga];
        tl[ty + j][tx] = ql[ga];
    }
    __syncthreads();
#pragma unroll
    for (int j = 0; j < 32; j += 8) {
        size_t go = (size_t)(bh * HD_ + d0 + ty + j) * S_ + s0 + tx;
        vth[go] = th[tx][ty + j];
        vtl[go] = tl[tx][ty + j];
    }
}

// ---------------------------------------------------------------------------
// Tensor-core GEMM (bf16 split, 3 MMA): C = (Ah+Al)@(Bh+Bl)^T
// OUTB=0: fp32 C.  OUTB=1: bf16 hi/lo C (for qkv).
// ---------------------------------------------------------------------------
#define PITCH 40
#define BUFB  (128 * PITCH * 2)
#define STAGEB (4 * BUFB)
#define GEMM_SMEM (2 * STAGEB)

template <int OUTB>
__global__ void __launch_bounds__(256, 2) mma_gemm(
    const __nv_bfloat16* __restrict__ Ah, const __nv_bfloat16* __restrict__ Al,
    const __nv_bfloat16* __restrict__ Bh, const __nv_bfloat16* __restrict__ Bl,
    float* __restrict__ C, __nv_bfloat16* __restrict__ Ch,
    __nv_bfloat16* __restrict__ Cl, int M, int N, int K)
{
    extern __shared__ __align__(16) uint8_t smem[];
    const uint32_t sbase = smem_to_u32(smem);
    const int tid = threadIdx.x, lane = tid & 31, wid = tid >> 5;
    const int wr = wid & 3, wc = wid >> 2;
    const int bm = blockIdx.y * 128, bn = blockIdx.x * 128;
    const int NK = K / 32;

    float acc[2][8][4];
#pragma unroll
    for (int i = 0; i < 2; i++)
#pragma unroll
        for (int j = 0; j < 8; j++)
#pragma unroll
            for (int r = 0; r < 4; r++) acc[i][j][r] = 0.f;

#define ISSUE(kt, stg) do {                                                    \
        uint32_t sb_ = sbase + (stg) * STAGEB;                                 \
        _Pragma("unroll")                                                      \
        for (int hf = 0; hf < 2; hf++) {                                       \
            int c = tid + hf * 256;                                            \
            int row = c >> 2, colc = (c & 3) * 8;                              \
            uint32_t doff = (uint32_t)(row * (PITCH * 2) + colc * 2);          \
            size_t ga = (size_t)(bm + row) * K + (kt) * 32 + colc;             \
            size_t gb = (size_t)(bn + row) * K + (kt) * 32 + colc;             \
            CP16(sb_ + 0 * BUFB + doff, Ah + ga);                              \
            CP16(sb_ + 1 * BUFB + doff, Al + ga);                              \
            CP16(sb_ + 2 * BUFB + doff, Bh + gb);                              \
            CP16(sb_ + 3 * BUFB + doff, Bl + gb);                              \
        }                                                                      \
        CP_COMMIT();                                                           \
    } while (0)

    ISSUE(0, 0);

    for (int kt = 0; kt < NK; kt++) {
        const int cur = kt & 1;
        if (kt + 1 < NK) {
            ISSUE(kt + 1, (kt + 1) & 1);
            asm volatile("cp.async.wait_group 1;");
        } else {
            asm volatile("cp.async.wait_group 0;");
        }
        __syncthreads();

        const uint32_t sA_h = sbase + cur * STAGEB;
        const uint32_t sA_l = sA_h + BUFB;
        const uint32_t sB_h = sA_h + 2 * BUFB;
        const uint32_t sB_l = sA_h + 3 * BUFB;

#pragma unroll
        for (int ks = 0; ks < 2; ks++) {
            uint32_t ah[2][4], al[2][4];
#pragma unroll
            for (int i = 0; i < 2; i++) {
                uint32_t ra = (uint32_t)((wr * 32 + i * 16 + (lane & 15)) * (PITCH * 2)
                              + (ks * 16 + ((lane >> 4) << 3)) * 2);
                LDSM4(ah[i], sA_h + ra);
                LDSM4(al[i], sA_l + ra);
            }
#pragma unroll
            for (int jp = 0; jp < 4; jp++) {
                uint32_t rowb = (uint32_t)(wc * 64 + jp * 16 + ((lane >> 4) << 3) + (lane & 7));
                uint32_t colb = (uint32_t)(ks * 16 + (((lane >> 3) & 1) << 3));
                uint32_t rb = rowb * (PITCH * 2) + colb * 2;
                uint32_t bh4[4], bl4[4];
                LDSM4(bh4, sB_h + rb);
                LDSM4(bl4, sB_l + rb);
#pragma unroll
                for (int i = 0; i < 2; i++) {
                    MMA16816(acc[i][jp * 2],     ah[i], bh4[0], bh4[1]);
                    MMA16816(acc[i][jp * 2],     al[i], bh4[0], bh4[1]);
                    MMA16816(acc[i][jp * 2],     ah[i], bl4[0], bl4[1]);
                    MMA16816(acc[i][jp * 2 + 1], ah[i], bh4[2], bh4[3]);
                    MMA16816(acc[i][jp * 2 + 1], al[i], bh4[2], bh4[3]);
                    MMA16816(acc[i][jp * 2 + 1], ah[i], bl4[2], bl4[3]);
                }
            }
        }
        __syncthreads();
    }

#pragma unroll
    for (int i = 0; i < 2; i++) {
        int mrow = bm + wr * 32 + i * 16 + (lane >> 2);
#pragma unroll
        for (int j = 0; j < 8; j++) {
            int ncol = bn + wc * 64 + j * 8 + (lane & 3) * 2;
            if (OUTB == 0) {
                *(float2*)(C + (size_t)mrow * N + ncol) =
                    make_float2(acc[i][j][0], acc[i][j][1]);
                *(float2*)(C + (size_t)(mrow + 8) * N + ncol) =
                    make_float2(acc[i][j][2], acc[i][j][3]);
            } else {
                __nv_bfloat16 h0, h1, l0, l1;
                bf16_split(acc[i][j][0], h0, l0);
                bf16_split(acc[i][j][1], h1, l1);
                *(__nv_bfloat162*)(Ch + (size_t)mrow * N + ncol) = __nv_bfloat162(h0, h1);
                *(__nv_bfloat162*)(Cl + (size_t)mrow * N + ncol) = __nv_bfloat162(l0, l1);
                bf16_split(acc[i][j][2], h0, l0);
                bf16_split(acc[i][j][3], h1, l1);
                *(__nv_bfloat162*)(Ch + (size_t)(mrow + 8) * N + ncol) = __nv_bfloat162(h0, h1);
                *(__nv_bfloat162*)(Cl + (size_t)(mrow + 8) * N + ncol) = __nv_bfloat162(l0, l1);
            }
        }
    }
#undef ISSUE
}

// ---------------------------------------------------------------------------
// Lambda scalar
// ---------------------------------------------------------------------------
__global__ void lambda_kernel(const float* __restrict__ lq1, const float* __restrict__ lq2,
                              const float* __restrict__ lk1, const float* __restrict__ lk2)
{
    if (threadIdx.x == 0) {
        float d1 = 0.f, d2 = 0.f;
        for (int i = 0; i < HD_; i++) { d1 += lq1[i] * lk1[i]; d2 += lq2[i] * lk2[i]; }
        g_lam = expf(d1) - expf(d2) + 0.8f;
    }
}

// ---------------------------------------------------------------------------
// Tensor-core flash attention (split-bf16, 3-MMA for QK and PV).
// CTA: 128 q rows of one (b,h), half = blockIdx.z. 256 thr, 8 warps (m16 each).
// K tiles of 64 keys, double-buffered cp.async.
// smem: Qh[0] Ql[10240] | K stages at 20480 (+10240/stage, lo at +5120)
//       | Vt stages at 40960 (+16384/stage, lo at +8192, SW128 128B rows)
// ---------------------------------------------------------------------------
#define SQ_OFF 0
#define SK_OFF 20480
#define SV_OFF 40960
#define ATT_SMEM 73728
#define NT_ (S_ / 64)

__global__ void __launch_bounds__(256, 2) attn_mma(
    const __nv_bfloat16* __restrict__ qh, const __nv_bfloat16* __restrict__ ql,
    const __nv_bfloat16* __restrict__ vth, const __nv_bfloat16* __restrict__ vtl,
    float* __restrict__ O1, float* __restrict__ O2)
{
    extern __shared__ __align__(16) uint8_t smem[];
    const uint32_t sbase = smem_to_u32(smem);
    const int tid = threadIdx.x, lane = tid & 31, wr = tid >> 5;
    const int bh = blockIdx.y, b = bh >> 4, h = bh & 15;
    const int half = blockIdx.z, d0 = half << 5;
    const int q0 = blockIdx.x * 128;

    const size_t qkoff = (size_t)b * S_ * QKV_N + h * HD_ + d0;

    // ---- issue Q (group shared with tile 0) ----
#pragma unroll
    for (int rep = 0; rep < 2; rep++) {
        int idx = tid + rep * 256;            // 0..511
        int row = idx >> 2, ch = idx & 3;
        size_t g = qkoff + (size_t)(q0 + row) * QKV_N + ch * 8;
        uint32_t so = (uint32_t)(row * 80 + ch * 16);
        CP16(sbase + SQ_OFF + so, qh + g);
        CP16(sbase + SQ_OFF + 10240 + so, ql + g);
    }

    auto issue_tile = [&](int t, int stg) {
        uint32_t kb = sbase + SK_OFF + stg * 10240;
        {
            int row = tid >> 2, ch = tid & 3;
            size_t g = qkoff + (size_t)E_ + (size_t)(t * 64 + row) * QKV_N + ch * 8;
            uint32_t so = (uint32_t)(row * 80 + ch * 16);
            CP16(kb + so, qh + g);
            CP16(kb + 5120 + so, ql + g);
        }
        uint32_t vb = sbase + SV_OFF + stg * 16384;
#pragma unroll
        for (int rep = 0; rep < 2; rep++) {
            int idx = tid + rep * 256;
            int vrow = idx >> 3, vch = idx & 7;
            size_t g = (size_t)(bh * HD_ + vrow) * S_ + t * 64 + vch * 8;
            uint32_t so = SMEM_SWIZZLE_128B((uint32_t)(vrow * 128 + vch * 16));
            CP16(vb + so, vth + g);
            CP16(vb + 8192 + so, vtl + g);
        }
        CP_COMMIT();
    };

    issue_tile(0, 0);
    issue_tile(1, 1);

    float o[8][4];
#pragma unroll
    for (int j = 0; j < 8; j++)
#pragma unroll
        for (int r = 0; r < 4; r++) o[j][r] = 0.f;
    float m0 = -1e30f, m1 = -1e30f, l0 = 0.f, l1 = 0.f;
    uint32_t ah[2][4], al[2][4];

    const float CSC = 0.125f * 1.4426950408889634f;

    for (int t = 0; t < NT_; t++) {
        if (t < NT_ - 1) asm volatile("cp.async.wait_group 1;");
        else             asm volatile("cp.async.wait_group 0;");
        __syncthreads();

        if (t == 0) {
#pragma unroll
            for (int ks = 0; ks < 2; ks++) {
                uint32_t ra = sbase + SQ_OFF + (uint32_t)((wr * 16 + (lane & 15)) * 80
                              + (ks * 16 + ((lane >> 4) << 3)) * 2);
                LDSM4(ah[ks], ra);
                LDSM4(al[ks], ra + 10240);
            }
        }

        // ---- S = Q K^T (split-bf16) ----
        float s[8][4];
#pragma unroll
        for (int j = 0; j < 8; j++)
#pragma unroll
            for (int r = 0; r < 4; r++) s[j][r] = 0.f;

        const uint32_t kb = sbase + SK_OFF + (t & 1) * 10240;
#pragma unroll
        for (int ks = 0; ks < 2; ks++) {
#pragma unroll
            for (int jp = 0; jp < 4; jp++) {
                uint32_t ra = kb + (uint32_t)((jp * 16 + ((lane >> 4) << 3) + (lane & 7)) * 80
                              + (ks * 16 + (((lane >> 3) & 1) << 3)) * 2);
                uint32_t kh4[4], kl4[4];
                LDSM4(kh4, ra);
                LDSM4(kl4, ra + 5120);
                MMA16816(s[jp * 2],     ah[ks], kh4[0], kh4[1]);
                MMA16816(s[jp * 2],     al[ks], kh4[0], kh4[1]);
                MMA16816(s[jp * 2],     ah[ks], kl4[0], kl4[1]);
                MMA16816(s[jp * 2 + 1], ah[ks], kh4[2], kh4[3]);
                MMA16816(s[jp * 2 + 1], al[ks], kh4[2], kh4[3]);
                MMA16816(s[jp * 2 + 1], ah[ks], kl4[2], kl4[3]);
            }
        }

        // ---- online softmax ----
        float mx0 = -1e30f, mx1 = -1e30f;
#pragma unroll
        for (int j = 0; j < 8; j++) {
            s[j][0] *= CSC; s[j][1] *= CSC; s[j][2] *= CSC; s[j][3] *= CSC;
            mx0 = fmaxf(mx0, fmaxf(s[j][0], s[j][1]));
            mx1 = fmaxf(mx1, fmaxf(s[j][2], s[j][3]));
        }
        mx0 = fmaxf(mx0, __shfl_xor_sync(0xffffffffu, mx0, 1));
        mx0 = fmaxf(mx0, __shfl_xor_sync(0xffffffffu, mx0, 2));
        mx1 = fmaxf(mx1, __shfl_xor_sync(0xffffffffu, mx1, 1));
        mx1 = fmaxf(mx1, __shfl_xor_sync(0xffffffffu, mx1, 2));
        const float nm0 = fmaxf(m0, mx0), nm1 = fmaxf(m1, mx1);
        const float sc0 = exp2f(m0 - nm0), sc1 = exp2f(m1 - nm1);
        m0 = nm0; m1 = nm1;
        l0 *= sc0; l1 *= sc1;
#pragma unroll
        for (int j = 0; j < 8; j++) {
            o[j][0] *= sc0; o[j][1] *= sc0; o[j][2] *= sc1; o[j][3] *= sc1;
        }

        uint32_t pah[4][4], pal[4][4];
#pragma unroll
        for (int kp = 0; kp < 4; kp++) {
#pragma unroll
            for (int fi = 0; fi < 2; fi++) {
                const int jf = kp * 2 + fi;
                float p0 = exp2f(s[jf][0] - nm0);
                float p1 = exp2f(s[jf][1] - nm0);
                float p2 = exp2f(s[jf][2] - nm1);
                float p3 = exp2f(s[jf][3] - nm1);
                l0 += p0 + p1; l1 += p2 + p3;
                float h0 = __bfloat162float(__float2bfloat16(p0));
                float h1 = __bfloat162float(__float2bfloat16(p1));
                float h2 = __bfloat162float(__float2bfloat16(p2));
                float h3 = __bfloat162float(__float2bfloat16(p3));
                PACKBF(pah[kp][fi * 2],     p0, p1);
                PACKBF(pah[kp][fi * 2 + 1], p2, p3);
                PACKBF(pal[kp][fi * 2],     p0 - h0, p1 - h1);
                PACKBF(pal[kp][fi * 2 + 1], p2 - h2, p3 - h3);
            }
        }

        // ---- O += P V (split-bf16) ----
        const uint32_t vb = sbase + SV_OFF + (t & 1) * 16384;
#pragma unroll
        for (int kp = 0; kp < 4; kp++) {
#pragma unroll
            for (int jn = 0; jn < 4; jn++) {
                uint32_t va = vb + SMEM_SWIZZLE_128B(
                    (uint32_t)((jn * 16 + ((lane >> 4) << 3) + (lane & 7)) * 128
                               + (kp * 16 + (((lane >> 3) & 1) << 3)) * 2));
                uint32_t vh4[4], vl4[4];
                LDSM4(vh4, va);
                LDSM4(vl4, va + 8192);
                MMA16816(o[jn * 2],     pah[kp], vh4[0], vh4[1]);
                MMA16816(o[jn * 2],     pal[kp], vh4[0], vh4[1]);
                MMA16816(o[jn * 2],     pah[kp], vl4[0], vl4[1]);
                MMA16816(o[jn * 2 + 1], pah[kp], vh4[2], vh4[3]);
                MMA16816(o[jn * 2 + 1], pal[kp], vh4[2], vh4[3]);
                MMA16816(o[jn * 2 + 1], pah[kp], vl4[2], vl4[3]);
            }
        }
        __syncthreads();
        if (t + 2 < NT_) issue_tile(t + 2, t & 1);
    }

    // ---- finalize ----
    l0 += __shfl_xor_sync(0xffffffffu, l0, 1);
    l0 += __shfl_xor_sync(0xffffffffu, l0, 2);
    l1 += __shfl_xor_sync(0xffffffffu, l1, 1);
    l1 += __shfl_xor_sync(0xffffffffu, l1, 2);
    const float inv0 = 1.f / l0, inv1 = 1.f / l1;
    const int g = lane >> 2, tq = lane & 3;
    float* Op = (half ? O2 : O1) + ((size_t)bh * S_ + q0 + wr * 16) * HD_;
#pragma unroll
    for (int jf = 0; jf < 8; jf++) {
        int col = jf * 8 + tq * 2;
        *(float2*)(Op + (size_t)g * HD_ + col) =
            make_float2(o[jf][0] * inv0, o[jf][1] * inv0);
        *(float2*)(Op + (size_t)(g + 8) * HD_ + col) =
            make_float2(o[jf][2] * inv1, o[jf][3] * inv1);
    }
}

// ---------------------------------------------------------------------------
// Combine + RMSNorm + scrambled reshape -> bf16 hi/lo
// ---------------------------------------------------------------------------
__global__ __launch_bounds__(256) void combine_kernel(
    const float* __restrict__ O1, const float* __restrict__ O2,
    const float* __restrict__ normw,
    __nv_bfloat16* __restrict__ X2h, __nv_bfloat16* __restrict__ X2l)
{
    const int r = blockIdx.x * 8 + (threadIdx.x >> 5);
    const int lane = threadIdx.x & 31;
    const int bh = r >> 11;
    const int s = r & 2047;
    const int b = bh >> 4, h = bh & 15;

    const float lam = g_lam;
    const float* p1 = O1 + (size_t)r * HD_;
    const float* p2 = O2 + (size_t)r * HD_;

    float a0 = p1[lane]      - lam * p2[lane];
    float a1 = p1[lane + 32] - lam * p2[lane + 32];

    float ss = a0 * a0 + a1 * a1;
#pragma unroll
    for (int off = 16; off > 0; off >>= 1) ss += __shfl_xor_sync(0xffffffffu, ss, off);

    const float inv = rsqrtf(ss * (1.f / 64.f) + 1e-6f);
    const float w0 = normw[h * HD_ + lane];
    const float w1 = normw[h * HD_ + lane + 32];
    const float scale = 1.0f - 0.8f;

    float v0 = a0 * inv * w0 * scale;
    float v1 = a1 * inv * w1 * scale;

    const size_t xb = (size_t)b * S_ * E_;
    const int shi = s >> 10, slo = s & 1023;
    size_t i0 = xb + (size_t)(lane * 32 + h * 2 + shi) * E_ + slo;
    size_t i1 = xb + (size_t)((lane + 32) * 32 + h * 2 + shi) * E_ + slo;

    __nv_bfloat16 h0, h1, l0, l1;
    bf16_split(v0, h0, l0);
    bf16_split(v1, h1, l1);
    X2h[i0] = h0; X2l[i0] = l0;
    X2h[i1] = h1; X2l[i1] = l1;
}

// ---------------------------------------------------------------------------
// Launch
// ---------------------------------------------------------------------------
extern "C" void kernel_launch(void* const* d_in, const int* in_sizes, int n_in,
                              void* d_out, int out_size)
{
    const float* x     = (const float*)d_in[0];
    const float* w_qkv = (const float*)d_in[1];
    const float* wo    = (const float*)d_in[2];
    const float* lq1   = (const float*)d_in[3];
    const float* lq2   = (const float*)d_in[4];
    const float* lk1   = (const float*)d_in[5];
    const float* lk2   = (const float*)d_in[6];
    const float* normw = (const float*)d_in[7];
    float* out = (float*)d_out;

    float *p_O1, *p_O2;
    cudaGetSymbolAddress((void**)&p_O1, g_O1);
    cudaGetSymbolAddress((void**)&p_O2, g_O2);
    __nv_bfloat16 *p_xh, *p_xl, *p_qh, *p_ql, *p_vth, *p_vtl;
    __nv_bfloat16 *p_X2h, *p_X2l, *p_wqh, *p_wql, *p_woh, *p_wol;
    cudaGetSymbolAddress((void**)&p_xh, g_xh);
    cudaGetSymbolAddress((void**)&p_xl, g_xl);
    cudaGetSymbolAddress((void**)&p_qh, g_qkvh);
    cudaGetSymbolAddress((void**)&p_ql, g_qkvl);
    cudaGetSymbolAddress((void**)&p_vth, g_vth);
    cudaGetSymbolAddress((void**)&p_vtl, g_vtl);
    cudaGetSymbolAddress((void**)&p_X2h, g_X2h);
    cudaGetSymbolAddress((void**)&p_X2l, g_X2l);
    cudaGetSymbolAddress((void**)&p_wqh, g_wqkvT_hi);
    cudaGetSymbolAddress((void**)&p_wql, g_wqkvT_lo);
    cudaGetSymbolAddress((void**)&p_woh, g_woT_hi);
    cudaGetSymbolAddress((void**)&p_wol, g_woT_lo);

    cudaFuncSetAttribute(mma_gemm<0>, cudaFuncAttributeMaxDynamicSharedMemorySize, GEMM_SMEM);
    cudaFuncSetAttribute(mma_gemm<1>, cudaFuncAttributeMaxDynamicSharedMemorySize, GEMM_SMEM);
    cudaFuncSetAttribute(attn_mma, cudaFuncAttributeMaxDynamicSharedMemorySize, ATT_SMEM);

    // 0) splits
    split_kernel<<<(M_TOK * E_) / (256 * 4), 256>>>(x, p_xh, p_xl);
    transpose_split<<<dim3(QKV_N / 32, E_ / 32), 256>>>(w_qkv, p_wqh, p_wql, E_, QKV_N);
    transpose_split<<<dim3(E_ / 32, E_ / 32), 256>>>(wo, p_woh, p_wol, E_, E_);

    // 1) QKV projection -> bf16 hi/lo
    mma_gemm<1><<<dim3(QKV_N / 128, M_TOK / 128), 256, GEMM_SMEM>>>(
        p_xh, p_xl, p_wqh, p_wql, nullptr, p_qh, p_ql, M_TOK, QKV_N, E_);

    // 2) V transpose + lambda
    vtrans_kernel<<<dim3(S_ / 32, HD_ / 32, B_ * H_), 256>>>(p_qh, p_ql, p_vth, p_vtl);
    lambda_kernel<<<1, 32>>>(lq1, lq2, lk1, lk2);

    // 3) tensor-core attention, both halves
    attn_mma<<<dim3(S_ / 128, B_ * H_, 2), 256, ATT_SMEM>>>(
        p_qh, p_ql, p_vth, p_vtl, p_O1, p_O2);

    // 4) combine + RMSNorm + scrambled reshape (emits bf16 hi/lo)
    combine_kernel<<<(B_ * H_ * S_) / 8, 256>>>(p_O1, p_O2, normw, p_X2h, p_X2l);

    // 5) output projection -> fp32 d_out
    mma_gemm<0><<<dim3(E_ / 128, M_TOK / 128), 256, GEMM_SMEM>>>(
        p_X2h, p_X2l, p_woh, p_wol, out, nullptr, nullptr, M_TOK, E_, E_);
}

// round 7
// speedup vs baseline: 4.3440x; 1.0716x over previous
#include <cuda_runtime.h>
#include <cuda_bf16.h>
#include <math.h>
#include <stdint.h>

// Problem constants
#define B_  2
#define S_  2048
#define E_  1024
#define H_  16
#define HD_ 64
#define M_TOK (B_ * S_)          // 4096
#define QKV_N (3 * E_)           // 3072

// ---------------------------------------------------------------------------
// Scratch (no allocation allowed -> __device__ globals)
// ---------------------------------------------------------------------------
__device__ float g_O1[B_ * H_ * S_ * HD_];
__device__ float g_O2[B_ * H_ * S_ * HD_];
__device__ float g_lam;
__device__ __nv_bfloat16 g_xh[M_TOK * E_];        // x split hi/lo
__device__ __nv_bfloat16 g_xl[M_TOK * E_];
__device__ __nv_bfloat16 g_qkvh[M_TOK * QKV_N];   // qkv split hi/lo
__device__ __nv_bfloat16 g_qkvl[M_TOK * QKV_N];
__device__ __nv_bfloat16 g_vth[B_ * H_ * HD_ * S_];  // V^T [b,h,d,s]
__device__ __nv_bfloat16 g_vtl[B_ * H_ * HD_ * S_];
__device__ __nv_bfloat16 g_X2h[M_TOK * E_];       // scrambled pre-wo hi/lo
__device__ __nv_bfloat16 g_X2l[M_TOK * E_];
__device__ __nv_bfloat16 g_wqkvT_hi[QKV_N * E_];
__device__ __nv_bfloat16 g_wqkvT_lo[QKV_N * E_];
__device__ __nv_bfloat16 g_woT_hi[E_ * E_];
__device__ __nv_bfloat16 g_woT_lo[E_ * E_];

// ---------------------------------------------------------------------------
// Helpers
// ---------------------------------------------------------------------------
__device__ __forceinline__ uint32_t smem_to_u32(const void* p) {
    uint32_t a;
    asm("{ .reg .u64 tmp; cvta.to.shared.u64 tmp, %1; cvt.u32.u64 %0, tmp; }"
        : "=r"(a) : "l"(p));
    return a;
}
#define CP16(daddr, gptr) \
    asm volatile("cp.async.cg.shared.global [%0], [%1], 16;" \
                 :: "r"(daddr), "l"(gptr))
#define CP_COMMIT() asm volatile("cp.async.commit_group;")
#define LDSM4(r, addr) \
    asm volatile("ldmatrix.sync.aligned.m8n8.x4.shared.b16 {%0,%1,%2,%3}, [%4];" \
                 : "=r"((r)[0]), "=r"((r)[1]), "=r"((r)[2]), "=r"((r)[3]) \
                 : "r"(addr))
#define MMA16816(d, a, b0_, b1_) \
    asm volatile("mma.sync.aligned.m16n8k16.row.col.f32.bf16.bf16.f32 " \
                 "{%0,%1,%2,%3}, {%4,%5,%6,%7}, {%8,%9}, {%0,%1,%2,%3};" \
                 : "+f"((d)[0]), "+f"((d)[1]), "+f"((d)[2]), "+f"((d)[3]) \
                 : "r"((a)[0]), "r"((a)[1]), "r"((a)[2]), "r"((a)[3]), \
                   "r"(b0_), "r"(b1_))
// pack two fp32 -> bf16x2 (lo = first arg, hi = second)
#define PACKBF(r, lo_, hi_) \
    asm("cvt.rn.bf16x2.f32 %0, %1, %2;" : "=r"(r) : "f"(hi_), "f"(lo_))
#define SMEM_SWIZZLE_128B(byte_offset) \
    ((byte_offset) ^ (((byte_offset) >> 3) & 0x70))

__device__ __forceinline__ void bf16_split(float v, __nv_bfloat16& h, __nv_bfloat16& l) {
    h = __float2bfloat16(v);
    l = __float2bfloat16(v - __bfloat162float(h));
}

// ---------------------------------------------------------------------------
// Weight transpose + bf16 hi/lo split:  in [K,N] fp32  ->  out [N,K] bf16 x2
// ---------------------------------------------------------------------------
__global__ __launch_bounds__(256) void transpose_split(
    const float* __restrict__ in, __nv_bfloat16* __restrict__ oh,
    __nv_bfloat16* __restrict__ ol, int K, int N)
{
    __shared__ float t[32][33];
    const int tx = threadIdx.x & 31, ty = threadIdx.x >> 5;
    const int n0 = blockIdx.x * 32, k0 = blockIdx.y * 32;
#pragma unroll
    for (int j = 0; j < 32; j += 8)
        t[ty + j][tx] = in[(size_t)(k0 + ty + j) * N + n0 + tx];
    __syncthreads();
#pragma unroll
    for (int j = 0; j < 32; j += 8) {
        float v = t[tx][ty + j];
        __nv_bfloat16 h, l; bf16_split(v, h, l);
        size_t o = (size_t)(n0 + ty + j) * K + k0 + tx;
        oh[o] = h; ol[o] = l;
    }
}

// ---------------------------------------------------------------------------
// Elementwise fp32 -> bf16 hi/lo split (for x)
// ---------------------------------------------------------------------------
__global__ __launch_bounds__(256) void split_kernel(
    const float* __restrict__ in, __nv_bfloat16* __restrict__ oh,
    __nv_bfloat16* __restrict__ ol)
{
    int i = (blockIdx.x * 256 + threadIdx.x) * 4;
    float4 v = *(const float4*)(in + i);
    __nv_bfloat16 h0, h1, h2, h3, l0, l1, l2, l3;
    bf16_split(v.x, h0, l0); bf16_split(v.y, h1, l1);
    bf16_split(v.z, h2, l2); bf16_split(v.w, h3, l3);
    __nv_bfloat162* ph = (__nv_bfloat162*)(oh + i);
    __nv_bfloat162* pl = (__nv_bfloat162*)(ol + i);
    ph[0] = __nv_bfloat162(h0, h1); ph[1] = __nv_bfloat162(h2, h3);
    pl[0] = __nv_bfloat162(l0, l1); pl[1] = __nv_bfloat162(l2, l3);
}

// ---------------------------------------------------------------------------
// V transpose (bf16 -> bf16): qkv v-part [b,s,h,d] -> [b,h,d,s], hi & lo
// ---------------------------------------------------------------------------
__global__ __launch_bounds__(256) void vtrans_kernel(
    const __nv_bfloat16* __restrict__ qh, const __nv_bfloat16* __restrict__ ql,
    __nv_bfloat16* __restrict__ vth, __nv_bfloat16* __restrict__ vtl)
{
    __shared__ __nv_bfloat16 th[32][33], tl[32][33];
    const int bh = blockIdx.z, b = bh >> 4, h = bh & 15;
    const int s0 = blockIdx.x * 32, d0 = blockIdx.y * 32;
    const int tx = threadIdx.x & 31, ty = threadIdx.x >> 5;
#pragma unroll
    for (int j = 0; j < 32; j += 8) {
        size_t ga = (size_t)(b * S_ + s0 + ty + j) * QKV_N + 2 * E_ + h * HD_ + d0 + tx;
        th[ty + j][tx] = qh[ga];
        tl[ty + j][tx] = ql[ga];
    }
    __syncthreads();
#pragma unroll
    for (int j = 0; j < 32; j += 8) {
        size_t go = (size_t)(bh * HD_ + d0 + ty + j) * S_ + s0 + tx;
        vth[go] = th[tx][ty + j];
        vtl[go] = tl[tx][ty + j];
    }
}

// ---------------------------------------------------------------------------
// Tensor-core GEMM (bf16 split, 3 MMA): C = (Ah+Al)@(Bh+Bl)^T
// MMAs round-robin across 4 accumulators to break RAW chains.
// OUTB=0: fp32 C.  OUTB=1: bf16 hi/lo C (for qkv).
// ---------------------------------------------------------------------------
#define PITCH 40
#define BUFB  (128 * PITCH * 2)
#define STAGEB (4 * BUFB)
#define GEMM_SMEM (2 * STAGEB)

template <int OUTB>
__global__ void __launch_bounds__(256, 2) mma_gemm(
    const __nv_bfloat16* __restrict__ Ah, const __nv_bfloat16* __restrict__ Al,
    const __nv_bfloat16* __restrict__ Bh, const __nv_bfloat16* __restrict__ Bl,
    float* __restrict__ C, __nv_bfloat16* __restrict__ Ch,
    __nv_bfloat16* __restrict__ Cl, int M, int N, int K)
{
    extern __shared__ __align__(16) uint8_t smem[];
    const uint32_t sbase = smem_to_u32(smem);
    const int tid = threadIdx.x, lane = tid & 31, wid = tid >> 5;
    const int wr = wid & 3, wc = wid >> 2;
    const int bm = blockIdx.y * 128, bn = blockIdx.x * 128;
    const int NK = K / 32;

    float acc[2][8][4];
#pragma unroll
    for (int i = 0; i < 2; i++)
#pragma unroll
        for (int j = 0; j < 8; j++)
#pragma unroll
            for (int r = 0; r < 4; r++) acc[i][j][r] = 0.f;

#define ISSUE(kt, stg) do {                                                    \
        uint32_t sb_ = sbase + (stg) * STAGEB;                                 \
        _Pragma("unroll")                                                      \
        for (int hf = 0; hf < 2; hf++) {                                       \
            int c = tid + hf * 256;                                            \
            int row = c >> 2, colc = (c & 3) * 8;                              \
            uint32_t doff = (uint32_t)(row * (PITCH * 2) + colc * 2);          \
            size_t ga = (size_t)(bm + row) * K + (kt) * 32 + colc;             \
            size_t gb = (size_t)(bn + row) * K + (kt) * 32 + colc;             \
            CP16(sb_ + 0 * BUFB + doff, Ah + ga);                              \
            CP16(sb_ + 1 * BUFB + doff, Al + ga);                              \
            CP16(sb_ + 2 * BUFB + doff, Bh + gb);                              \
            CP16(sb_ + 3 * BUFB + doff, Bl + gb);                              \
        }                                                                      \
        CP_COMMIT();                                                           \
    } while (0)

    ISSUE(0, 0);

    for (int kt = 0; kt < NK; kt++) {
        const int cur = kt & 1;
        if (kt + 1 < NK) {
            ISSUE(kt + 1, (kt + 1) & 1);
            asm volatile("cp.async.wait_group 1;");
        } else {
            asm volatile("cp.async.wait_group 0;");
        }
        __syncthreads();

        const uint32_t sA_h = sbase + cur * STAGEB;
        const uint32_t sA_l = sA_h + BUFB;
        const uint32_t sB_h = sA_h + 2 * BUFB;
        const uint32_t sB_l = sA_h + 3 * BUFB;

#pragma unroll
        for (int ks = 0; ks < 2; ks++) {
            uint32_t ah[2][4], al[2][4];
#pragma unroll
            for (int i = 0; i < 2; i++) {
                uint32_t ra = (uint32_t)((wr * 32 + i * 16 + (lane & 15)) * (PITCH * 2)
                              + (ks * 16 + ((lane >> 4) << 3)) * 2);
                LDSM4(ah[i], sA_h + ra);
                LDSM4(al[i], sA_l + ra);
            }
#pragma unroll
            for (int jp = 0; jp < 4; jp++) {
                uint32_t rowb = (uint32_t)(wc * 64 + jp * 16 + ((lane >> 4) << 3) + (lane & 7));
                uint32_t colb = (uint32_t)(ks * 16 + (((lane >> 3) & 1) << 3));
                uint32_t rb = rowb * (PITCH * 2) + colb * 2;
                uint32_t bh4[4], bl4[4];
                LDSM4(bh4, sB_h + rb);
                LDSM4(bl4, sB_l + rb);
                // round-robin over 4 accumulators: RAW distance 4
                MMA16816(acc[0][jp * 2],     ah[0], bh4[0], bh4[1]);
                MMA16816(acc[1][jp * 2],     ah[1], bh4[0], bh4[1]);
                MMA16816(acc[0][jp * 2 + 1], ah[0], bh4[2], bh4[3]);
                MMA16816(acc[1][jp * 2 + 1], ah[1], bh4[2], bh4[3]);
                MMA16816(acc[0][jp * 2],     al[0], bh4[0], bh4[1]);
                MMA16816(acc[1][jp * 2],     al[1], bh4[0], bh4[1]);
                MMA16816(acc[0][jp * 2 + 1], al[0], bh4[2], bh4[3]);
                MMA16816(acc[1][jp * 2 + 1], al[1], bh4[2], bh4[3]);
                MMA16816(acc[0][jp * 2],     ah[0], bl4[0], bl4[1]);
                MMA16816(acc[1][jp * 2],     ah[1], bl4[0], bl4[1]);
                MMA16816(acc[0][jp * 2 + 1], ah[0], bl4[2], bl4[3]);
                MMA16816(acc[1][jp * 2 + 1], ah[1], bl4[2], bl4[3]);
            }
        }
        __syncthreads();
    }

#pragma unroll
    for (int i = 0; i < 2; i++) {
        int mrow = bm + wr * 32 + i * 16 + (lane >> 2);
#pragma unroll
        for (int j = 0; j < 8; j++) {
            int ncol = bn + wc * 64 + j * 8 + (lane & 3) * 2;
            if (OUTB == 0) {
                *(float2*)(C + (size_t)mrow * N + ncol) =
                    make_float2(acc[i][j][0], acc[i][j][1]);
                *(float2*)(C + (size_t)(mrow + 8) * N + ncol) =
                    make_float2(acc[i][j][2], acc[i][j][3]);
            } else {
                __nv_bfloat16 h0, h1, l0, l1;
                bf16_split(acc[i][j][0], h0, l0);
                bf16_split(acc[i][j][1], h1, l1);
                *(__nv_bfloat162*)(Ch + (size_t)mrow * N + ncol) = __nv_bfloat162(h0, h1);
                *(__nv_bfloat162*)(Cl + (size_t)mrow * N + ncol) = __nv_bfloat162(l0, l1);
                bf16_split(acc[i][j][2], h0, l0);
                bf16_split(acc[i][j][3], h1, l1);
                *(__nv_bfloat162*)(Ch + (size_t)(mrow + 8) * N + ncol) = __nv_bfloat162(h0, h1);
                *(__nv_bfloat162*)(Cl + (size_t)(mrow + 8) * N + ncol) = __nv_bfloat162(l0, l1);
            }
        }
    }
#undef ISSUE
}

// ---------------------------------------------------------------------------
// Lambda scalar
// ---------------------------------------------------------------------------
__global__ void lambda_kernel(const float* __restrict__ lq1, const float* __restrict__ lq2,
                              const float* __restrict__ lk1, const float* __restrict__ lk2)
{
    if (threadIdx.x == 0) {
        float d1 = 0.f, d2 = 0.f;
        for (int i = 0; i < HD_; i++) { d1 += lq1[i] * lk1[i]; d2 += lq2[i] * lk2[i]; }
        g_lam = expf(d1) - expf(d2) + 0.8f;
    }
}

// ---------------------------------------------------------------------------
// Tensor-core flash attention (split-bf16, 3-MMA for QK and PV).
// MMAs round-robin across accumulators; softmax scale fused into exp2 FMA.
// ---------------------------------------------------------------------------
#define SQ_OFF 0
#define SK_OFF 20480
#define SV_OFF 40960
#define ATT_SMEM 73728
#define NT_ (S_ / 64)

__global__ void __launch_bounds__(256, 2) attn_mma(
    const __nv_bfloat16* __restrict__ qh, const __nv_bfloat16* __restrict__ ql,
    const __nv_bfloat16* __restrict__ vth, const __nv_bfloat16* __restrict__ vtl,
    float* __restrict__ O1, float* __restrict__ O2)
{
    extern __shared__ __align__(16) uint8_t smem[];
    const uint32_t sbase = smem_to_u32(smem);
    const int tid = threadIdx.x, lane = tid & 31, wr = tid >> 5;
    const int bh = blockIdx.y, b = bh >> 4, h = bh & 15;
    const int half = blockIdx.z, d0 = half << 5;
    const int q0 = blockIdx.x * 128;

    const size_t qkoff = (size_t)b * S_ * QKV_N + h * HD_ + d0;

    // ---- issue Q (group shared with tile 0) ----
#pragma unroll
    for (int rep = 0; rep < 2; rep++) {
        int idx = tid + rep * 256;            // 0..511
        int row = idx >> 2, ch = idx & 3;
        size_t g = qkoff + (size_t)(q0 + row) * QKV_N + ch * 8;
        uint32_t so = (uint32_t)(row * 80 + ch * 16);
        CP16(sbase + SQ_OFF + so, qh + g);
        CP16(sbase + SQ_OFF + 10240 + so, ql + g);
    }

    auto issue_tile = [&](int t, int stg) {
        uint32_t kb = sbase + SK_OFF + stg * 10240;
        {
            int row = tid >> 2, ch = tid & 3;
            size_t g = qkoff + (size_t)E_ + (size_t)(t * 64 + row) * QKV_N + ch * 8;
            uint32_t so = (uint32_t)(row * 80 + ch * 16);
            CP16(kb + so, qh + g);
            CP16(kb + 5120 + so, ql + g);
        }
        uint32_t vb = sbase + SV_OFF + stg * 16384;
#pragma unroll
        for (int rep = 0; rep < 2; rep++) {
            int idx = tid + rep * 256;
            int vrow = idx >> 3, vch = idx & 7;
            size_t g = (size_t)(bh * HD_ + vrow) * S_ + t * 64 + vch * 8;
            uint32_t so = SMEM_SWIZZLE_128B((uint32_t)(vrow * 128 + vch * 16));
            CP16(vb + so, vth + g);
            CP16(vb + 8192 + so, vtl + g);
        }
        CP_COMMIT();
    };

    issue_tile(0, 0);
    issue_tile(1, 1);

    float o[8][4];
#pragma unroll
    for (int j = 0; j < 8; j++)
#pragma unroll
        for (int r = 0; r < 4; r++) o[j][r] = 0.f;
    float m0 = -1e30f, m1 = -1e30f, l0 = 0.f, l1 = 0.f;
    uint32_t ah[2][4], al[2][4];

    const float CSC = 0.125f * 1.4426950408889634f;

    for (int t = 0; t < NT_; t++) {
        if (t < NT_ - 1) asm volatile("cp.async.wait_group 1;");
        else             asm volatile("cp.async.wait_group 0;");
        __syncthreads();

        if (t == 0) {
#pragma unroll
            for (int ks = 0; ks < 2; ks++) {
                uint32_t ra = sbase + SQ_OFF + (uint32_t)((wr * 16 + (lane & 15)) * 80
                              + (ks * 16 + ((lane >> 4) << 3)) * 2);
                LDSM4(ah[ks], ra);
                LDSM4(al[ks], ra + 10240);
            }
        }

        // ---- S = Q K^T (split-bf16) ----
        float s[8][4];
#pragma unroll
        for (int j = 0; j < 8; j++)
#pragma unroll
            for (int r = 0; r < 4; r++) s[j][r] = 0.f;

        const uint32_t kb = sbase + SK_OFF + (t & 1) * 10240;
#pragma unroll
        for (int ks = 0; ks < 2; ks++) {
#pragma unroll
            for (int jp = 0; jp < 4; jp++) {
                uint32_t ra = kb + (uint32_t)((jp * 16 + ((lane >> 4) << 3) + (lane & 7)) * 80
                              + (ks * 16 + (((lane >> 3) & 1) << 3)) * 2);
                uint32_t kh4[4], kl4[4];
                LDSM4(kh4, ra);
                LDSM4(kl4, ra + 5120);
                // interleave: RAW distance 2
                MMA16816(s[jp * 2],     ah[ks], kh4[0], kh4[1]);
                MMA16816(s[jp * 2 + 1], ah[ks], kh4[2], kh4[3]);
                MMA16816(s[jp * 2],     al[ks], kh4[0], kh4[1]);
                MMA16816(s[jp * 2 + 1], al[ks], kh4[2], kh4[3]);
                MMA16816(s[jp * 2],     ah[ks], kl4[0], kl4[1]);
                MMA16816(s[jp * 2 + 1], ah[ks], kl4[2], kl4[3]);
            }
        }

        // ---- online softmax (scale fused into exp2 fma; max kept scaled) ----
        float mx0 = -1e30f, mx1 = -1e30f;
#pragma unroll
        for (int j = 0; j < 8; j++) {
            mx0 = fmaxf(mx0, fmaxf(s[j][0], s[j][1]));
            mx1 = fmaxf(mx1, fmaxf(s[j][2], s[j][3]));
        }
        mx0 = fmaxf(mx0, __shfl_xor_sync(0xffffffffu, mx0, 1));
        mx0 = fmaxf(mx0, __shfl_xor_sync(0xffffffffu, mx0, 2));
        mx1 = fmaxf(mx1, __shfl_xor_sync(0xffffffffu, mx1, 1));
        mx1 = fmaxf(mx1, __shfl_xor_sync(0xffffffffu, mx1, 2));
        const float nm0 = fmaxf(m0, mx0 * CSC), nm1 = fmaxf(m1, mx1 * CSC);
        const float sc0 = exp2f(m0 - nm0), sc1 = exp2f(m1 - nm1);
        m0 = nm0; m1 = nm1;
        l0 *= sc0; l1 *= sc1;
#pragma unroll
        for (int j = 0; j < 8; j++) {
            o[j][0] *= sc0; o[j][1] *= sc0; o[j][2] *= sc1; o[j][3] *= sc1;
        }

        uint32_t pah[4][4], pal[4][4];
#pragma unroll
        for (int kp = 0; kp < 4; kp++) {
#pragma unroll
            for (int fi = 0; fi < 2; fi++) {
                const int jf = kp * 2 + fi;
                float p0 = exp2f(fmaf(s[jf][0], CSC, -nm0));
                float p1 = exp2f(fmaf(s[jf][1], CSC, -nm0));
                float p2 = exp2f(fmaf(s[jf][2], CSC, -nm1));
                float p3 = exp2f(fmaf(s[jf][3], CSC, -nm1));
                l0 += p0 + p1; l1 += p2 + p3;
                float h0 = __bfloat162float(__float2bfloat16(p0));
                float h1 = __bfloat162float(__float2bfloat16(p1));
                float h2 = __bfloat162float(__float2bfloat16(p2));
                float h3 = __bfloat162float(__float2bfloat16(p3));
                PACKBF(pah[kp][fi * 2],     p0, p1);
                PACKBF(pah[kp][fi * 2 + 1], p2, p3);
                PACKBF(pal[kp][fi * 2],     p0 - h0, p1 - h1);
                PACKBF(pal[kp][fi * 2 + 1], p2 - h2, p3 - h3);
            }
        }

        // ---- O += P V (split-bf16) ----
        const uint32_t vb = sbase + SV_OFF + (t & 1) * 16384;
#pragma unroll
        for (int kp = 0; kp < 4; kp++) {
#pragma unroll
            for (int jn = 0; jn < 4; jn++) {
                uint32_t va = vb + SMEM_SWIZZLE_128B(
                    (uint32_t)((jn * 16 + ((lane >> 4) << 3) + (lane & 7)) * 128
                               + (kp * 16 + (((lane >> 3) & 1) << 3)) * 2));
                uint32_t vh4[4], vl4[4];
                LDSM4(vh4, va);
                LDSM4(vl4, va + 8192);
                // interleave: RAW distance 2
                MMA16816(o[jn * 2],     pah[kp], vh4[0], vh4[1]);
                MMA16816(o[jn * 2 + 1], pah[kp], vh4[2], vh4[3]);
                MMA16816(o[jn * 2],     pal[kp], vh4[0], vh4[1]);
                MMA16816(o[jn * 2 + 1], pal[kp], vh4[2], vh4[3]);
                MMA16816(o[jn * 2],     pah[kp], vl4[0], vl4[1]);
                MMA16816(o[jn * 2 + 1], pah[kp], vl4[2], vl4[3]);
            }
        }
        __syncthreads();
        if (t + 2 < NT_) issue_tile(t + 2, t & 1);
    }

    // ---- finalize ----
    l0 += __shfl_xor_sync(0xffffffffu, l0, 1);
    l0 += __shfl_xor_sync(0xffffffffu, l0, 2);
    l1 += __shfl_xor_sync(0xffffffffu, l1, 1);
    l1 += __shfl_xor_sync(0xffffffffu, l1, 2);
    const float inv0 = 1.f / l0, inv1 = 1.f / l1;
    const int g = lane >> 2, tq = lane & 3;
    float* Op = (half ? O2 : O1) + ((size_t)bh * S_ + q0 + wr * 16) * HD_;
#pragma unroll
    for (int jf = 0; jf < 8; jf++) {
        int col = jf * 8 + tq * 2;
        *(float2*)(Op + (size_t)g * HD_ + col) =
            make_float2(o[jf][0] * inv0, o[jf][1] * inv0);
        *(float2*)(Op + (size_t)(g + 8) * HD_ + col) =
            make_float2(o[jf][2] * inv1, o[jf][3] * inv1);
    }
}

// ---------------------------------------------------------------------------
// Combine + RMSNorm + scrambled reshape -> bf16 hi/lo.
// SMEM-transposed version: coalesced loads AND coalesced 16B stores.
// Block = 256 thr handles 32 s-rows x 64 d of one (b,h).
// grid = (S/32, B*H)
// ---------------------------------------------------------------------------
__global__ __launch_bounds__(256) void combine_kernel(
    const float* __restrict__ O1, const float* __restrict__ O2,
    const float* __restrict__ normw,
    __nv_bfloat16* __restrict__ X2h, __nv_bfloat16* __restrict__ X2l)
{
    __shared__ ushort smh[64][40], sml[64][40];

    const int bh = blockIdx.y, b = bh >> 4, h = bh & 15;
    const int s0 = blockIdx.x * 32;
    const int tid = threadIdx.x;
    const int sr = tid >> 3;              // 0..31 (s row)
    const int dp = (tid & 7) * 8;         // d base 0..56

    const float lam = g_lam;
    const size_t rbase = ((size_t)bh * S_ + s0 + sr) * HD_ + dp;

    float a[8];
    float ss = 0.f;
#pragma unroll
    for (int c = 0; c < 2; c++) {
        float4 v1 = *(const float4*)(O1 + rbase + c * 4);
        float4 v2 = *(const float4*)(O2 + rbase + c * 4);
        a[c * 4 + 0] = v1.x - lam * v2.x;
        a[c * 4 + 1] = v1.y - lam * v2.y;
        a[c * 4 + 2] = v1.z - lam * v2.z;
        a[c * 4 + 3] = v1.w - lam * v2.w;
#pragma unroll
        for (int j = 0; j < 4; j++) ss += a[c * 4 + j] * a[c * 4 + j];
    }
    // reduce over the 8 threads sharing this s-row (consecutive lanes)
    ss += __shfl_xor_sync(0xffffffffu, ss, 1);
    ss += __shfl_xor_sync(0xffffffffu, ss, 2);
    ss += __shfl_xor_sync(0xffffffffu, ss, 4);
    const float inv = rsqrtf(ss * (1.f / 64.f) + 1e-6f) * (1.0f - 0.8f);

#pragma unroll
    for (int j = 0; j < 8; j++) {
        float v = a[j] * inv * normw[h * HD_ + dp + j];
        __nv_bfloat16 hh, ll; bf16_split(v, hh, ll);
        smh[dp + j][sr] = __bfloat16_as_ushort(hh);
        sml[dp + j][sr] = __bfloat16_as_ushort(ll);
    }
    __syncthreads();

    // write out: row d -> X2[(d*32 + h*2 + shi)][slo0..+32], 16B per thread
    const int dr = tid >> 2, chunk = tid & 3;     // dr 0..63, chunk 0..3
    const int shi = s0 >> 10, slo0 = s0 & 1023;
    const size_t obase = (size_t)b * S_ * E_ + (size_t)(dr * 32 + h * 2 + shi) * E_
                       + slo0 + chunk * 8;
    *(uint4*)(X2h + obase) = *(const uint4*)(&smh[dr][chunk * 8]);
    *(uint4*)(X2l + obase) = *(const uint4*)(&sml[dr][chunk * 8]);
}

// ---------------------------------------------------------------------------
// Launch
// ---------------------------------------------------------------------------
extern "C" void kernel_launch(void* const* d_in, const int* in_sizes, int n_in,
                              void* d_out, int out_size)
{
    const float* x     = (const float*)d_in[0];
    const float* w_qkv = (const float*)d_in[1];
    const float* wo    = (const float*)d_in[2];
    const float* lq1   = (const float*)d_in[3];
    const float* lq2   = (const float*)d_in[4];
    const float* lk1   = (const float*)d_in[5];
    const float* lk2   = (const float*)d_in[6];
    const float* normw = (const float*)d_in[7];
    float* out = (float*)d_out;

    float *p_O1, *p_O2;
    cudaGetSymbolAddress((void**)&p_O1, g_O1);
    cudaGetSymbolAddress((void**)&p_O2, g_O2);
    __nv_bfloat16 *p_xh, *p_xl, *p_qh, *p_ql, *p_vth, *p_vtl;
    __nv_bfloat16 *p_X2h, *p_X2l, *p_wqh, *p_wql, *p_woh, *p_wol;
    cudaGetSymbolAddress((void**)&p_xh, g_xh);
    cudaGetSymbolAddress((void**)&p_xl, g_xl);
    cudaGetSymbolAddress((void**)&p_qh, g_qkvh);
    cudaGetSymbolAddress((void**)&p_ql, g_qkvl);
    cudaGetSymbolAddress((void**)&p_vth, g_vth);
    cudaGetSymbolAddress((void**)&p_vtl, g_vtl);
    cudaGetSymbolAddress((void**)&p_X2h, g_X2h);
    cudaGetSymbolAddress((void**)&p_X2l, g_X2l);
    cudaGetSymbolAddress((void**)&p_wqh, g_wqkvT_hi);
    cudaGetSymbolAddress((void**)&p_wql, g_wqkvT_lo);
    cudaGetSymbolAddress((void**)&p_woh, g_woT_hi);
    cudaGetSymbolAddress((void**)&p_wol, g_woT_lo);

    cudaFuncSetAttribute(mma_gemm<0>, cudaFuncAttributeMaxDynamicSharedMemorySize, GEMM_SMEM);
    cudaFuncSetAttribute(mma_gemm<1>, cudaFuncAttributeMaxDynamicSharedMemorySize, GEMM_SMEM);
    cudaFuncSetAttribute(attn_mma, cudaFuncAttributeMaxDynamicSharedMemorySize, ATT_SMEM);

    // 0) splits
    split_kernel<<<(M_TOK * E_) / (256 * 4), 256>>>(x, p_xh, p_xl);
    transpose_split<<<dim3(QKV_N / 32, E_ / 32), 256>>>(w_qkv, p_wqh, p_wql, E_, QKV_N);
    transpose_split<<<dim3(E_ / 32, E_ / 32), 256>>>(wo, p_woh, p_wol, E_, E_);

    // 1) QKV projection -> bf16 hi/lo
    mma_gemm<1><<<dim3(QKV_N / 128, M_TOK / 128), 256, GEMM_SMEM>>>(
        p_xh, p_xl, p_wqh, p_wql, nullptr, p_qh, p_ql, M_TOK, QKV_N, E_);

    // 2) V transpose + lambda
    vtrans_kernel<<<dim3(S_ / 32, HD_ / 32, B_ * H_), 256>>>(p_qh, p_ql, p_vth, p_vtl);
    lambda_kernel<<<1, 32>>>(lq1, lq2, lk1, lk2);

    // 3) tensor-core attention, both halves
    attn_mma<<<dim3(S_ / 128, B_ * H_, 2), 256, ATT_SMEM>>>(
        p_qh, p_ql, p_vth, p_vtl, p_O1, p_O2);

    // 4) combine + RMSNorm + scrambled reshape (emits bf16 hi/lo)
    combine_kernel<<<dim3(S_ / 32, B_ * H_), 256>>>(p_O1, p_O2, normw, p_X2h, p_X2l);

    // 5) output projection -> fp32 d_out
    mma_gemm<0><<<dim3(E_ / 128, M_TOK / 128), 256, GEMM_SMEM>>>(
        p_X2h, p_X2l, p_woh, p_wol, out, nullptr, nullptr, M_TOK, E_, E_);
}

// round 8
// speedup vs baseline: 6.3437x; 1.4603x over previous
#include <cuda_runtime.h>
#include <cuda_bf16.h>
#include <cuda_fp16.h>
#include <math.h>
#include <stdint.h>

// Problem constants
#define B_  2
#define S_  2048
#define E_  1024
#define H_  16
#define HD_ 64
#define M_TOK (B_ * S_)          // 4096
#define QKV_N (3 * E_)           // 3072

// ---------------------------------------------------------------------------
// Scratch (no allocation allowed -> __device__ globals)
// ---------------------------------------------------------------------------
__device__ float g_O1[B_ * H_ * S_ * HD_];
__device__ float g_O2[B_ * H_ * S_ * HD_];
__device__ float g_lam;
__device__ __nv_bfloat16 g_xh[M_TOK * E_];        // x split hi/lo
__device__ __nv_bfloat16 g_xl[M_TOK * E_];
__device__ __half g_qkv16[M_TOK * QKV_N];         // qkv fp16 (single)
__device__ __half g_vt16[B_ * H_ * HD_ * S_];     // V^T [b,h,d,s] fp16
__device__ __nv_bfloat16 g_X2h[M_TOK * E_];       // scrambled pre-wo hi/lo
__device__ __nv_bfloat16 g_X2l[M_TOK * E_];
__device__ __nv_bfloat16 g_wqkvT_hi[QKV_N * E_];
__device__ __nv_bfloat16 g_wqkvT_lo[QKV_N * E_];
__device__ __nv_bfloat16 g_woT_hi[E_ * E_];
__device__ __nv_bfloat16 g_woT_lo[E_ * E_];

// ---------------------------------------------------------------------------
// Helpers
// ---------------------------------------------------------------------------
__device__ __forceinline__ uint32_t smem_to_u32(const void* p) {
    uint32_t a;
    asm("{ .reg .u64 tmp; cvta.to.shared.u64 tmp, %1; cvt.u32.u64 %0, tmp; }"
        : "=r"(a) : "l"(p));
    return a;
}
#define CP16(daddr, gptr) \
    asm volatile("cp.async.cg.shared.global [%0], [%1], 16;" \
                 :: "r"(daddr), "l"(gptr))
#define CP_COMMIT() asm volatile("cp.async.commit_group;")
#define LDSM4(r, addr) \
    asm volatile("ldmatrix.sync.aligned.m8n8.x4.shared.b16 {%0,%1,%2,%3}, [%4];" \
                 : "=r"((r)[0]), "=r"((r)[1]), "=r"((r)[2]), "=r"((r)[3]) \
                 : "r"(addr))
#define MMA16816(d, a, b0_, b1_) \
    asm volatile("mma.sync.aligned.m16n8k16.row.col.f32.bf16.bf16.f32 " \
                 "{%0,%1,%2,%3}, {%4,%5,%6,%7}, {%8,%9}, {%0,%1,%2,%3};" \
                 : "+f"((d)[0]), "+f"((d)[1]), "+f"((d)[2]), "+f"((d)[3]) \
                 : "r"((a)[0]), "r"((a)[1]), "r"((a)[2]), "r"((a)[3]), \
                   "r"(b0_), "r"(b1_))
#define MMAF16(d, a, b0_, b1_) \
    asm volatile("mma.sync.aligned.m16n8k16.row.col.f32.f16.f16.f32 " \
                 "{%0,%1,%2,%3}, {%4,%5,%6,%7}, {%8,%9}, {%0,%1,%2,%3};" \
                 : "+f"((d)[0]), "+f"((d)[1]), "+f"((d)[2]), "+f"((d)[3]) \
                 : "r"((a)[0]), "r"((a)[1]), "r"((a)[2]), "r"((a)[3]), \
                   "r"(b0_), "r"(b1_))
// pack two fp32 -> f16x2 (lo = first value arg, hi = second)
#define PACKH(r, lo_, hi_) \
    asm("cvt.rn.f16x2.f32 %0, %1, %2;" : "=r"(r) : "f"(hi_), "f"(lo_))
#define SMEM_SWIZZLE_128B(byte_offset) \
    ((byte_offset) ^ (((byte_offset) >> 3) & 0x70))

__device__ __forceinline__ void bf16_split(float v, __nv_bfloat16& h, __nv_bfloat16& l) {
    h = __float2bfloat16(v);
    l = __float2bfloat16(v - __bfloat162float(h));
}

// ---------------------------------------------------------------------------
// Weight transpose + bf16 hi/lo split:  in [K,N] fp32  ->  out [N,K] bf16 x2
// ---------------------------------------------------------------------------
__global__ __launch_bounds__(256) void transpose_split(
    const float* __restrict__ in, __nv_bfloat16* __restrict__ oh,
    __nv_bfloat16* __restrict__ ol, int K, int N)
{
    __shared__ float t[32][33];
    const int tx = threadIdx.x & 31, ty = threadIdx.x >> 5;
    const int n0 = blockIdx.x * 32, k0 = blockIdx.y * 32;
#pragma unroll
    for (int j = 0; j < 32; j += 8)
        t[ty + j][tx] = in[(size_t)(k0 + ty + j) * N + n0 + tx];
    __syncthreads();
#pragma unroll
    for (int j = 0; j < 32; j += 8) {
        float v = t[tx][ty + j];
        __nv_bfloat16 h, l; bf16_split(v, h, l);
        size_t o = (size_t)(n0 + ty + j) * K + k0 + tx;
        oh[o] = h; ol[o] = l;
    }
}

// ---------------------------------------------------------------------------
// Elementwise fp32 -> bf16 hi/lo split (for x)
// ---------------------------------------------------------------------------
__global__ __launch_bounds__(256) void split_kernel(
    const float* __restrict__ in, __nv_bfloat16* __restrict__ oh,
    __nv_bfloat16* __restrict__ ol)
{
    int i = (blockIdx.x * 256 + threadIdx.x) * 4;
    float4 v = *(const float4*)(in + i);
    __nv_bfloat16 h0, h1, h2, h3, l0, l1, l2, l3;
    bf16_split(v.x, h0, l0); bf16_split(v.y, h1, l1);
    bf16_split(v.z, h2, l2); bf16_split(v.w, h3, l3);
    __nv_bfloat162* ph = (__nv_bfloat162*)(oh + i);
    __nv_bfloat162* pl = (__nv_bfloat162*)(ol + i);
    ph[0] = __nv_bfloat162(h0, h1); ph[1] = __nv_bfloat162(h2, h3);
    pl[0] = __nv_bfloat162(l0, l1); pl[1] = __nv_bfloat162(l2, l3);
}

// ---------------------------------------------------------------------------
// V transpose (fp16): qkv v-part [b,s,h,d] -> [b,h,d,s]
// ---------------------------------------------------------------------------
__global__ __launch_bounds__(256) void vtrans_kernel(
    const __half* __restrict__ q16, __half* __restrict__ vt16)
{
    __shared__ __half t[32][33];
    const int bh = blockIdx.z, b = bh >> 4, h = bh & 15;
    const int s0 = blockIdx.x * 32, d0 = blockIdx.y * 32;
    const int tx = threadIdx.x & 31, ty = threadIdx.x >> 5;
#pragma unroll
    for (int j = 0; j < 32; j += 8) {
        size_t ga = (size_t)(b * S_ + s0 + ty + j) * QKV_N + 2 * E_ + h * HD_ + d0 + tx;
        t[ty + j][tx] = q16[ga];
    }
    __syncthreads();
#pragma unroll
    for (int j = 0; j < 32; j += 8) {
        size_t go = (size_t)(bh * HD_ + d0 + ty + j) * S_ + s0 + tx;
        vt16[go] = t[tx][ty + j];
    }
}

// ---------------------------------------------------------------------------
// Tensor-core GEMM (bf16 split, 3 MMA): C = (Ah+Al)@(Bh+Bl)^T
// OUTF=0: fp32 C.  OUTF=1: fp16 C (for qkv).
// ---------------------------------------------------------------------------
#define PITCH 40
#define BUFB  (128 * PITCH * 2)
#define STAGEB (4 * BUFB)
#define GEMM_SMEM (2 * STAGEB)

template <int OUTF>
__global__ void __launch_bounds__(256, 2) mma_gemm(
    const __nv_bfloat16* __restrict__ Ah, const __nv_bfloat16* __restrict__ Al,
    const __nv_bfloat16* __restrict__ Bh, const __nv_bfloat16* __restrict__ Bl,
    float* __restrict__ C, __half* __restrict__ Cf, int M, int N, int K)
{
    extern __shared__ __align__(16) uint8_t smem[];
    const uint32_t sbase = smem_to_u32(smem);
    const int tid = threadIdx.x, lane = tid & 31, wid = tid >> 5;
    const int wr = wid & 3, wc = wid >> 2;
    const int bm = blockIdx.y * 128, bn = blockIdx.x * 128;
    const int NK = K / 32;

    float acc[2][8][4];
#pragma unroll
    for (int i = 0; i < 2; i++)
#pragma unroll
        for (int j = 0; j < 8; j++)
#pragma unroll
            for (int r = 0; r < 4; r++) acc[i][j][r] = 0.f;

#define ISSUE(kt, stg) do {                                                    \
        uint32_t sb_ = sbase + (stg) * STAGEB;                                 \
        _Pragma("unroll")                                                      \
        for (int hf = 0; hf < 2; hf++) {                                       \
            int c = tid + hf * 256;                                            \
            int row = c >> 2, colc = (c & 3) * 8;                              \
            uint32_t doff = (uint32_t)(row * (PITCH * 2) + colc * 2);          \
            size_t ga = (size_t)(bm + row) * K + (kt) * 32 + colc;             \
            size_t gb = (size_t)(bn + row) * K + (kt) * 32 + colc;             \
            CP16(sb_ + 0 * BUFB + doff, Ah + ga);                              \
            CP16(sb_ + 1 * BUFB + doff, Al + ga);                              \
            CP16(sb_ + 2 * BUFB + doff, Bh + gb);                              \
            CP16(sb_ + 3 * BUFB + doff, Bl + gb);                              \
        }                                                                      \
        CP_COMMIT();                                                           \
    } while (0)

    ISSUE(0, 0);

    for (int kt = 0; kt < NK; kt++) {
        const int cur = kt & 1;
        if (kt + 1 < NK) {
            ISSUE(kt + 1, (kt + 1) & 1);
            asm volatile("cp.async.wait_group 1;");
        } else {
            asm volatile("cp.async.wait_group 0;");
        }
        __syncthreads();

        const uint32_t sA_h = sbase + cur * STAGEB;
        const uint32_t sA_l = sA_h + BUFB;
        const uint32_t sB_h = sA_h + 2 * BUFB;
        const uint32_t sB_l = sA_h + 3 * BUFB;

#pragma unroll
        for (int ks = 0; ks < 2; ks++) {
            uint32_t ah[2][4], al[2][4];
#pragma unroll
            for (int i = 0; i < 2; i++) {
                uint32_t ra = (uint32_t)((wr * 32 + i * 16 + (lane & 15)) * (PITCH * 2)
                              + (ks * 16 + ((lane >> 4) << 3)) * 2);
                LDSM4(ah[i], sA_h + ra);
                LDSM4(al[i], sA_l + ra);
            }
#pragma unroll
            for (int jp = 0; jp < 4; jp++) {
                uint32_t rowb = (uint32_t)(wc * 64 + jp * 16 + ((lane >> 4) << 3) + (lane & 7));
                uint32_t colb = (uint32_t)(ks * 16 + (((lane >> 3) & 1) << 3));
                uint32_t rb = rowb * (PITCH * 2) + colb * 2;
                uint32_t bh4[4], bl4[4];
                LDSM4(bh4, sB_h + rb);
                LDSM4(bl4, sB_l + rb);
                MMA16816(acc[0][jp * 2],     ah[0], bh4[0], bh4[1]);
                MMA16816(acc[1][jp * 2],     ah[1], bh4[0], bh4[1]);
                MMA16816(acc[0][jp * 2 + 1], ah[0], bh4[2], bh4[3]);
                MMA16816(acc[1][jp * 2 + 1], ah[1], bh4[2], bh4[3]);
                MMA16816(acc[0][jp * 2],     al[0], bh4[0], bh4[1]);
                MMA16816(acc[1][jp * 2],     al[1], bh4[0], bh4[1]);
                MMA16816(acc[0][jp * 2 + 1], al[0], bh4[2], bh4[3]);
                MMA16816(acc[1][jp * 2 + 1], al[1], bh4[2], bh4[3]);
                MMA16816(acc[0][jp * 2],     ah[0], bl4[0], bl4[1]);
                MMA16816(acc[1][jp * 2],     ah[1], bl4[0], bl4[1]);
                MMA16816(acc[0][jp * 2 + 1], ah[0], bl4[2], bl4[3]);
                MMA16816(acc[1][jp * 2 + 1], ah[1], bl4[2], bl4[3]);
            }
        }
        __syncthreads();
    }

#pragma unroll
    for (int i = 0; i < 2; i++) {
        int mrow = bm + wr * 32 + i * 16 + (lane >> 2);
#pragma unroll
        for (int j = 0; j < 8; j++) {
            int ncol = bn + wc * 64 + j * 8 + (lane & 3) * 2;
            if (OUTF == 0) {
                *(float2*)(C + (size_t)mrow * N + ncol) =
                    make_float2(acc[i][j][0], acc[i][j][1]);
                *(float2*)(C + (size_t)(mrow + 8) * N + ncol) =
                    make_float2(acc[i][j][2], acc[i][j][3]);
            } else {
                *(__half2*)(Cf + (size_t)mrow * N + ncol) =
                    __floats2half2_rn(acc[i][j][0], acc[i][j][1]);
                *(__half2*)(Cf + (size_t)(mrow + 8) * N + ncol) =
                    __floats2half2_rn(acc[i][j][2], acc[i][j][3]);
            }
        }
    }
#undef ISSUE
}

// ---------------------------------------------------------------------------
// Lambda scalar
// ---------------------------------------------------------------------------
__global__ void lambda_kernel(const float* __restrict__ lq1, const float* __restrict__ lq2,
                              const float* __restrict__ lk1, const float* __restrict__ lk2)
{
    if (threadIdx.x == 0) {
        float d1 = 0.f, d2 = 0.f;
        for (int i = 0; i < HD_; i++) { d1 += lq1[i] * lk1[i]; d2 += lq2[i] * lk2[i]; }
        g_lam = expf(d1) - expf(d2) + 0.8f;
    }
}

// ---------------------------------------------------------------------------
// Tensor-core flash attention, single-pass fp16 (q,k,P,V all fp16; fp32 accum).
// CTA: 128 q rows of one (b,h), half = blockIdx.z. 256 thr, 8 warps (m16 each).
// smem: Q[0,10240) pitch-80 | K stages 10240+stg*5120 | Vt stages 20480+stg*8192
// ---------------------------------------------------------------------------
#define SQ_OFF 0
#define SK_OFF 10240
#define SV_OFF 20480
#define ATT_SMEM 36864
#define NT_ (S_ / 64)

__global__ void __launch_bounds__(256, 2) attn_mma(
    const __half* __restrict__ q16, const __half* __restrict__ vt16,
    float* __restrict__ O1, float* __restrict__ O2)
{
    extern __shared__ __align__(16) uint8_t smem[];
    const uint32_t sbase = smem_to_u32(smem);
    const int tid = threadIdx.x, lane = tid & 31, wr = tid >> 5;
    const int bh = blockIdx.y, b = bh >> 4, h = bh & 15;
    const int half = blockIdx.z, d0 = half << 5;
    const int q0 = blockIdx.x * 128;

    const size_t qkoff = (size_t)b * S_ * QKV_N + h * HD_ + d0;

    // ---- issue Q (grouped with tile 0) ----
#pragma unroll
    for (int rep = 0; rep < 2; rep++) {
        int idx = tid + rep * 256;            // 0..511
        int row = idx >> 2, ch = idx & 3;
        size_t g = qkoff + (size_t)(q0 + row) * QKV_N + ch * 8;
        CP16(sbase + SQ_OFF + (uint32_t)(row * 80 + ch * 16), q16 + g);
    }

    auto issue_tile = [&](int t, int stg) {
        uint32_t kb = sbase + SK_OFF + stg * 5120;
        {
            int row = tid >> 2, ch = tid & 3;
            size_t g = qkoff + (size_t)E_ + (size_t)(t * 64 + row) * QKV_N + ch * 8;
            CP16(kb + (uint32_t)(row * 80 + ch * 16), q16 + g);
        }
        uint32_t vb = sbase + SV_OFF + stg * 8192;
#pragma unroll
        for (int rep = 0; rep < 2; rep++) {
            int idx = tid + rep * 256;
            int vrow = idx >> 3, vch = idx & 7;
            size_t g = (size_t)(bh * HD_ + vrow) * S_ + t * 64 + vch * 8;
            CP16(vb + SMEM_SWIZZLE_128B((uint32_t)(vrow * 128 + vch * 16)), vt16 + g);
        }
        CP_COMMIT();
    };

    issue_tile(0, 0);
    issue_tile(1, 1);

    float o[8][4];
#pragma unroll
    for (int j = 0; j < 8; j++)
#pragma unroll
        for (int r = 0; r < 4; r++) o[j][r] = 0.f;
    float m0 = -1e30f, m1 = -1e30f, l0 = 0.f, l1 = 0.f;
    uint32_t ah[2][4];

    const float CSC = 0.125f * 1.4426950408889634f;

    for (int t = 0; t < NT_; t++) {
        if (t < NT_ - 1) asm volatile("cp.async.wait_group 1;");
        else             asm volatile("cp.async.wait_group 0;");
        __syncthreads();

        if (t == 0) {
#pragma unroll
            for (int ks = 0; ks < 2; ks++) {
                uint32_t ra = sbase + SQ_OFF + (uint32_t)((wr * 16 + (lane & 15)) * 80
                              + (ks * 16 + ((lane >> 4) << 3)) * 2);
                LDSM4(ah[ks], ra);
            }
        }

        // ---- S = Q K^T (fp16) ----
        float s[8][4];
#pragma unroll
        for (int j = 0; j < 8; j++)
#pragma unroll
            for (int r = 0; r < 4; r++) s[j][r] = 0.f;

        const uint32_t kb = sbase + SK_OFF + (t & 1) * 5120;
#pragma unroll
        for (int ks = 0; ks < 2; ks++) {
#pragma unroll
            for (int jp = 0; jp < 4; jp++) {
                uint32_t ra = kb + (uint32_t)((jp * 16 + ((lane >> 4) << 3) + (lane & 7)) * 80
                              + (ks * 16 + (((lane >> 3) & 1) << 3)) * 2);
                uint32_t kh4[4];
                LDSM4(kh4, ra);
                MMAF16(s[jp * 2],     ah[ks], kh4[0], kh4[1]);
                MMAF16(s[jp * 2 + 1], ah[ks], kh4[2], kh4[3]);
            }
        }

        // ---- online softmax (scale fused into exp2 fma) ----
        float mx0 = -1e30f, mx1 = -1e30f;
#pragma unroll
        for (int j = 0; j < 8; j++) {
            mx0 = fmaxf(mx0, fmaxf(s[j][0], s[j][1]));
            mx1 = fmaxf(mx1, fmaxf(s[j][2], s[j][3]));
        }
        mx0 = fmaxf(mx0, __shfl_xor_sync(0xffffffffu, mx0, 1));
        mx0 = fmaxf(mx0, __shfl_xor_sync(0xffffffffu, mx0, 2));
        mx1 = fmaxf(mx1, __shfl_xor_sync(0xffffffffu, mx1, 1));
        mx1 = fmaxf(mx1, __shfl_xor_sync(0xffffffffu, mx1, 2));
        const float nm0 = fmaxf(m0, mx0 * CSC), nm1 = fmaxf(m1, mx1 * CSC);
        const float sc0 = exp2f(m0 - nm0), sc1 = exp2f(m1 - nm1);
        m0 = nm0; m1 = nm1;
        l0 *= sc0; l1 *= sc1;
#pragma unroll
        for (int j = 0; j < 8; j++) {
            o[j][0] *= sc0; o[j][1] *= sc0; o[j][2] *= sc1; o[j][3] *= sc1;
        }

        uint32_t pah[4][4];
#pragma unroll
        for (int kp = 0; kp < 4; kp++) {
#pragma unroll
            for (int fi = 0; fi < 2; fi++) {
                const int jf = kp * 2 + fi;
                float p0 = exp2f(fmaf(s[jf][0], CSC, -nm0));
                float p1 = exp2f(fmaf(s[jf][1], CSC, -nm0));
                float p2 = exp2f(fmaf(s[jf][2], CSC, -nm1));
                float p3 = exp2f(fmaf(s[jf][3], CSC, -nm1));
                l0 += p0 + p1; l1 += p2 + p3;
                PACKH(pah[kp][fi * 2],     p0, p1);
                PACKH(pah[kp][fi * 2 + 1], p2, p3);
            }
        }

        // ---- O += P V (fp16) ----
        const uint32_t vb = sbase + SV_OFF + (t & 1) * 8192;
#pragma unroll
        for (int kp = 0; kp < 4; kp++) {
#pragma unroll
            for (int jn = 0; jn < 4; jn++) {
                uint32_t va = vb + SMEM_SWIZZLE_128B(
                    (uint32_t)((jn * 16 + ((lane >> 4) << 3) + (lane & 7)) * 128
                               + (kp * 16 + (((lane >> 3) & 1) << 3)) * 2));
                uint32_t vh4[4];
                LDSM4(vh4, va);
                MMAF16(o[jn * 2],     pah[kp], vh4[0], vh4[1]);
                MMAF16(o[jn * 2 + 1], pah[kp], vh4[2], vh4[3]);
            }
        }
        __syncthreads();
        if (t + 2 < NT_) issue_tile(t + 2, t & 1);
    }

    // ---- finalize ----
    l0 += __shfl_xor_sync(0xffffffffu, l0, 1);
    l0 += __shfl_xor_sync(0xffffffffu, l0, 2);
    l1 += __shfl_xor_sync(0xffffffffu, l1, 1);
    l1 += __shfl_xor_sync(0xffffffffu, l1, 2);
    const float inv0 = 1.f / l0, inv1 = 1.f / l1;
    const int g = lane >> 2, tq = lane & 3;
    float* Op = (half ? O2 : O1) + ((size_t)bh * S_ + q0 + wr * 16) * HD_;
#pragma unroll
    for (int jf = 0; jf < 8; jf++) {
        int col = jf * 8 + tq * 2;
        *(float2*)(Op + (size_t)g * HD_ + col) =
            make_float2(o[jf][0] * inv0, o[jf][1] * inv0);
        *(float2*)(Op + (size_t)(g + 8) * HD_ + col) =
            make_float2(o[jf][2] * inv1, o[jf][3] * inv1);
    }
}

// ---------------------------------------------------------------------------
// Combine + RMSNorm + scrambled reshape -> bf16 hi/lo (SMEM-transposed)
// ---------------------------------------------------------------------------
__global__ __launch_bounds__(256) void combine_kernel(
    const float* __restrict__ O1, const float* __restrict__ O2,
    const float* __restrict__ normw,
    __nv_bfloat16* __restrict__ X2h, __nv_bfloat16* __restrict__ X2l)
{
    __shared__ ushort smh[64][40], sml[64][40];

    const int bh = blockIdx.y, b = bh >> 4, h = bh & 15;
    const int s0 = blockIdx.x * 32;
    const int tid = threadIdx.x;
    const int sr = tid >> 3;
    const int dp = (tid & 7) * 8;

    const float lam = g_lam;
    const size_t rbase = ((size_t)bh * S_ + s0 + sr) * HD_ + dp;

    float a[8];
    float ss = 0.f;
#pragma unroll
    for (int c = 0; c < 2; c++) {
        float4 v1 = *(const float4*)(O1 + rbase + c * 4);
        float4 v2 = *(const float4*)(O2 + rbase + c * 4);
        a[c * 4 + 0] = v1.x - lam * v2.x;
        a[c * 4 + 1] = v1.y - lam * v2.y;
        a[c * 4 + 2] = v1.z - lam * v2.z;
        a[c * 4 + 3] = v1.w - lam * v2.w;
#pragma unroll
        for (int j = 0; j < 4; j++) ss += a[c * 4 + j] * a[c * 4 + j];
    }
    ss += __shfl_xor_sync(0xffffffffu, ss, 1);
    ss += __shfl_xor_sync(0xffffffffu, ss, 2);
    ss += __shfl_xor_sync(0xffffffffu, ss, 4);
    const float inv = rsqrtf(ss * (1.f / 64.f) + 1e-6f) * (1.0f - 0.8f);

#pragma unroll
    for (int j = 0; j < 8; j++) {
        float v = a[j] * inv * normw[h * HD_ + dp + j];
        __nv_bfloat16 hh, ll; bf16_split(v, hh, ll);
        smh[dp + j][sr] = __bfloat16_as_ushort(hh);
        sml[dp + j][sr] = __bfloat16_as_ushort(ll);
    }
    __syncthreads();

    const int dr = tid >> 2, chunk = tid & 3;
    const int shi = s0 >> 10, slo0 = s0 & 1023;
    const size_t obase = (size_t)b * S_ * E_ + (size_t)(dr * 32 + h * 2 + shi) * E_
                       + slo0 + chunk * 8;
    *(uint4*)(X2h + obase) = *(const uint4*)(&smh[dr][chunk * 8]);
    *(uint4*)(X2l + obase) = *(const uint4*)(&sml[dr][chunk * 8]);
}

// ---------------------------------------------------------------------------
// Launch
// ---------------------------------------------------------------------------
extern "C" void kernel_launch(void* const* d_in, const int* in_sizes, int n_in,
                              void* d_out, int out_size)
{
    const float* x     = (const float*)d_in[0];
    const float* w_qkv = (const float*)d_in[1];
    const float* wo    = (const float*)d_in[2];
    const float* lq1   = (const float*)d_in[3];
    const float* lq2   = (const float*)d_in[4];
    const float* lk1   = (const float*)d_in[5];
    const float* lk2   = (const float*)d_in[6];
    const float* normw = (const float*)d_in[7];
    float* out = (float*)d_out;

    float *p_O1, *p_O2;
    cudaGetSymbolAddress((void**)&p_O1, g_O1);
    cudaGetSymbolAddress((void**)&p_O2, g_O2);
    __half *p_q16, *p_vt16;
    cudaGetSymbolAddress((void**)&p_q16, g_qkv16);
    cudaGetSymbolAddress((void**)&p_vt16, g_vt16);
    __nv_bfloat16 *p_xh, *p_xl, *p_X2h, *p_X2l, *p_wqh, *p_wql, *p_woh, *p_wol;
    cudaGetSymbolAddress((void**)&p_xh, g_xh);
    cudaGetSymbolAddress((void**)&p_xl, g_xl);
    cudaGetSymbolAddress((void**)&p_X2h, g_X2h);
    cudaGetSymbolAddress((void**)&p_X2l, g_X2l);
    cudaGetSymbolAddress((void**)&p_wqh, g_wqkvT_hi);
    cudaGetSymbolAddress((void**)&p_wql, g_wqkvT_lo);
    cudaGetSymbolAddress((void**)&p_woh, g_woT_hi);
    cudaGetSymbolAddress((void**)&p_wol, g_woT_lo);

    cudaFuncSetAttribute(mma_gemm<0>, cudaFuncAttributeMaxDynamicSharedMemorySize, GEMM_SMEM);
    cudaFuncSetAttribute(mma_gemm<1>, cudaFuncAttributeMaxDynamicSharedMemorySize, GEMM_SMEM);
    cudaFuncSetAttribute(attn_mma, cudaFuncAttributeMaxDynamicSharedMemorySize, ATT_SMEM);

    // 0) splits
    split_kernel<<<(M_TOK * E_) / (256 * 4), 256>>>(x, p_xh, p_xl);
    transpose_split<<<dim3(QKV_N / 32, E_ / 32), 256>>>(w_qkv, p_wqh, p_wql, E_, QKV_N);
    transpose_split<<<dim3(E_ / 32, E_ / 32), 256>>>(wo, p_woh, p_wol, E_, E_);

    // 1) QKV projection -> fp16
    mma_gemm<1><<<dim3(QKV_N / 128, M_TOK / 128), 256, GEMM_SMEM>>>(
        p_xh, p_xl, p_wqh, p_wql, nullptr, p_q16, M_TOK, QKV_N, E_);

    // 2) V transpose + lambda
    vtrans_kernel<<<dim3(S_ / 32, HD_ / 32, B_ * H_), 256>>>(p_q16, p_vt16);
    lambda_kernel<<<1, 32>>>(lq1, lq2, lk1, lk2);

    // 3) fp16 tensor-core attention, both halves
    attn_mma<<<dim3(S_ / 128, B_ * H_, 2), 256, ATT_SMEM>>>(
        p_q16, p_vt16, p_O1, p_O2);

    // 4) combine + RMSNorm + scrambled reshape (emits bf16 hi/lo)
    combine_kernel<<<dim3(S_ / 32, B_ * H_), 256>>>(p_O1, p_O2, normw, p_X2h, p_X2l);

    // 5) output projection -> fp32 d_out
    mma_gemm<0><<<dim3(E_ / 128, M_TOK / 128), 256, GEMM_SMEM>>>(
        p_X2h, p_X2l, p_woh, p_wol, out, nullptr, M_TOK, E_, E_);
}

// round 9
// speedup vs baseline: 9.6289x; 1.5179x over previous
#include <cuda_runtime.h>
#include <cuda_bf16.h>
#include <cuda_fp16.h>
#include <math.h>
#include <stdint.h>

// Problem constants
#define B_  2
#define S_  2048
#define E_  1024
#define H_  16
#define HD_ 64
#define M_TOK (B_ * S_)          // 4096
#define QKV_N (3 * E_)           // 3072

// ---------------------------------------------------------------------------
// Scratch (no allocation allowed -> __device__ globals)
// ---------------------------------------------------------------------------
__device__ float g_O1[B_ * H_ * S_ * HD_];
__device__ float g_O2[B_ * H_ * S_ * HD_];
__device__ float g_lam;
__device__ __half g_x16[M_TOK * E_];              // x fp16
__device__ __half g_qkv16[M_TOK * QKV_N];         // qkv fp16
__device__ __half g_vt16[B_ * H_ * HD_ * S_];     // V^T [b,h,d,s] fp16
__device__ __half g_X216[M_TOK * E_];             // scrambled pre-wo fp16
__device__ __half g_wqkvT16[QKV_N * E_];          // [3072,1024] K-major fp16
__device__ __half g_woT16[E_ * E_];               // [1024,1024] K-major fp16

// ---------------------------------------------------------------------------
// Helpers
// ---------------------------------------------------------------------------
__device__ __forceinline__ uint32_t smem_to_u32(const void* p) {
    uint32_t a;
    asm("{ .reg .u64 tmp; cvta.to.shared.u64 tmp, %1; cvt.u32.u64 %0, tmp; }"
        : "=r"(a) : "l"(p));
    return a;
}
#define CP16(daddr, gptr) \
    asm volatile("cp.async.cg.shared.global [%0], [%1], 16;" \
                 :: "r"(daddr), "l"(gptr))
#define CP_COMMIT() asm volatile("cp.async.commit_group;")
#define LDSM4(r, addr) \
    asm volatile("ldmatrix.sync.aligned.m8n8.x4.shared.b16 {%0,%1,%2,%3}, [%4];" \
                 : "=r"((r)[0]), "=r"((r)[1]), "=r"((r)[2]), "=r"((r)[3]) \
                 : "r"(addr))
#define MMAF16(d, a, b0_, b1_) \
    asm volatile("mma.sync.aligned.m16n8k16.row.col.f32.f16.f16.f32 " \
                 "{%0,%1,%2,%3}, {%4,%5,%6,%7}, {%8,%9}, {%0,%1,%2,%3};" \
                 : "+f"((d)[0]), "+f"((d)[1]), "+f"((d)[2]), "+f"((d)[3]) \
                 : "r"((a)[0]), "r"((a)[1]), "r"((a)[2]), "r"((a)[3]), \
                   "r"(b0_), "r"(b1_))
// pack two fp32 -> f16x2 (lo = first value arg, hi = second)
#define PACKH(r, lo_, hi_) \
    asm("cvt.rn.f16x2.f32 %0, %1, %2;" : "=r"(r) : "f"(hi_), "f"(lo_))
#define SMEM_SWIZZLE_128B(byte_offset) \
    ((byte_offset) ^ (((byte_offset) >> 3) & 0x70))

// ---------------------------------------------------------------------------
// Weight transpose + fp16 convert:  in [K,N] fp32  ->  out [N,K] fp16
// ---------------------------------------------------------------------------
__global__ __launch_bounds__(256) void transpose_f16(
    const float* __restrict__ in, __half* __restrict__ o16, int K, int N)
{
    __shared__ float t[32][33];
    const int tx = threadIdx.x & 31, ty = threadIdx.x >> 5;
    const int n0 = blockIdx.x * 32, k0 = blockIdx.y * 32;
#pragma unroll
    for (int j = 0; j < 32; j += 8)
        t[ty + j][tx] = in[(size_t)(k0 + ty + j) * N + n0 + tx];
    __syncthreads();
#pragma unroll
    for (int j = 0; j < 32; j += 8)
        o16[(size_t)(n0 + ty + j) * K + k0 + tx] = __float2half(t[tx][ty + j]);
}

// ---------------------------------------------------------------------------
// Elementwise fp32 -> fp16 (for x)
// ---------------------------------------------------------------------------
__global__ __launch_bounds__(256) void tof16_kernel(
    const float* __restrict__ in, __half* __restrict__ o16)
{
    int i = (blockIdx.x * 256 + threadIdx.x) * 4;
    float4 v = *(const float4*)(in + i);
    __half2* p = (__half2*)(o16 + i);
    p[0] = __floats2half2_rn(v.x, v.y);
    p[1] = __floats2half2_rn(v.z, v.w);
}

// ---------------------------------------------------------------------------
// V transpose (fp16): qkv v-part [b,s,h,d] -> [b,h,d,s]
// ---------------------------------------------------------------------------
__global__ __launch_bounds__(256) void vtrans_kernel(
    const __half* __restrict__ q16, __half* __restrict__ vt16)
{
    __shared__ __half t[32][33];
    const int bh = blockIdx.z, b = bh >> 4, h = bh & 15;
    const int s0 = blockIdx.x * 32, d0 = blockIdx.y * 32;
    const int tx = threadIdx.x & 31, ty = threadIdx.x >> 5;
#pragma unroll
    for (int j = 0; j < 32; j += 8) {
        size_t ga = (size_t)(b * S_ + s0 + ty + j) * QKV_N + 2 * E_ + h * HD_ + d0 + tx;
        t[ty + j][tx] = q16[ga];
    }
    __syncthreads();
#pragma unroll
    for (int j = 0; j < 32; j += 8) {
        size_t go = (size_t)(bh * HD_ + d0 + ty + j) * S_ + s0 + tx;
        vt16[go] = t[tx][ty + j];
    }
}

// ---------------------------------------------------------------------------
// Tensor-core GEMM, single-pass fp16: C = A @ B^T, fp32 accumulate.
// A: [M,K] fp16 row-major; B: [N,K] fp16 K-major.
// 128x128 tile, BK=32, 256 thr, 2-stage cp.async double buffer.
// OUTF=0: fp32 C.  OUTF=1: fp16 C.
// ---------------------------------------------------------------------------
#define PITCH 40
#define BUFB  (128 * PITCH * 2)       // 10240 B
#define STAGEB (2 * BUFB)             // 20480 B
#define GEMM_SMEM (2 * STAGEB)        // 40960 B

template <int OUTF>
__global__ void __launch_bounds__(256, 2) mma_gemm(
    const __half* __restrict__ A, const __half* __restrict__ Bm,
    float* __restrict__ C, __half* __restrict__ Cf, int M, int N, int K)
{
    extern __shared__ __align__(16) uint8_t smem[];
    const uint32_t sbase = smem_to_u32(smem);
    const int tid = threadIdx.x, lane = tid & 31, wid = tid >> 5;
    const int wr = wid & 3, wc = wid >> 2;
    const int bm = blockIdx.y * 128, bn = blockIdx.x * 128;
    const int NK = K / 32;

    float acc[2][8][4];
#pragma unroll
    for (int i = 0; i < 2; i++)
#pragma unroll
        for (int j = 0; j < 8; j++)
#pragma unroll
            for (int r = 0; r < 4; r++) acc[i][j][r] = 0.f;

#define ISSUE(kt, stg) do {                                                    \
        uint32_t sb_ = sbase + (stg) * STAGEB;                                 \
        _Pragma("unroll")                                                      \
        for (int hf = 0; hf < 2; hf++) {                                       \
            int c = tid + hf * 256;                                            \
            int row = c >> 2, colc = (c & 3) * 8;                              \
            uint32_t doff = (uint32_t)(row * (PITCH * 2) + colc * 2);          \
            CP16(sb_ + doff, A + (size_t)(bm + row) * K + (kt) * 32 + colc);   \
            CP16(sb_ + BUFB + doff,                                            \
                 Bm + (size_t)(bn + row) * K + (kt) * 32 + colc);              \
        }                                                                      \
        CP_COMMIT();                                                           \
    } while (0)

    ISSUE(0, 0);

    for (int kt = 0; kt < NK; kt++) {
        const int cur = kt & 1;
        if (kt + 1 < NK) {
            ISSUE(kt + 1, (kt + 1) & 1);
            asm volatile("cp.async.wait_group 1;");
        } else {
            asm volatile("cp.async.wait_group 0;");
        }
        __syncthreads();

        const uint32_t sA = sbase + cur * STAGEB;
        const uint32_t sB = sA + BUFB;

#pragma unroll
        for (int ks = 0; ks < 2; ks++) {
            uint32_t ah[2][4];
#pragma unroll
            for (int i = 0; i < 2; i++) {
                uint32_t ra = (uint32_t)((wr * 32 + i * 16 + (lane & 15)) * (PITCH * 2)
                              + (ks * 16 + ((lane >> 4) << 3)) * 2);
                LDSM4(ah[i], sA + ra);
            }
#pragma unroll
            for (int jp = 0; jp < 4; jp++) {
                uint32_t rowb = (uint32_t)(wc * 64 + jp * 16 + ((lane >> 4) << 3) + (lane & 7));
                uint32_t colb = (uint32_t)(ks * 16 + (((lane >> 3) & 1) << 3));
                uint32_t rb = rowb * (PITCH * 2) + colb * 2;
                uint32_t bh4[4];
                LDSM4(bh4, sB + rb);
                MMAF16(acc[0][jp * 2],     ah[0], bh4[0], bh4[1]);
                MMAF16(acc[1][jp * 2],     ah[1], bh4[0], bh4[1]);
                MMAF16(acc[0][jp * 2 + 1], ah[0], bh4[2], bh4[3]);
                MMAF16(acc[1][jp * 2 + 1], ah[1], bh4[2], bh4[3]);
            }
        }
        __syncthreads();
    }

#pragma unroll
    for (int i = 0; i < 2; i++) {
        int mrow = bm + wr * 32 + i * 16 + (lane >> 2);
#pragma unroll
        for (int j = 0; j < 8; j++) {
            int ncol = bn + wc * 64 + j * 8 + (lane & 3) * 2;
            if (OUTF == 0) {
                *(float2*)(C + (size_t)mrow * N + ncol) =
                    make_float2(acc[i][j][0], acc[i][j][1]);
                *(float2*)(C + (size_t)(mrow + 8) * N + ncol) =
                    make_float2(acc[i][j][2], acc[i][j][3]);
            } else {
                *(__half2*)(Cf + (size_t)mrow * N + ncol) =
                    __floats2half2_rn(acc[i][j][0], acc[i][j][1]);
                *(__half2*)(Cf + (size_t)(mrow + 8) * N + ncol) =
                    __floats2half2_rn(acc[i][j][2], acc[i][j][3]);
            }
        }
    }
#undef ISSUE
}

// ---------------------------------------------------------------------------
// Lambda scalar
// ---------------------------------------------------------------------------
__global__ void lambda_kernel(const float* __restrict__ lq1, const float* __restrict__ lq2,
                              const float* __restrict__ lk1, const float* __restrict__ lk2)
{
    if (threadIdx.x == 0) {
        float d1 = 0.f, d2 = 0.f;
        for (int i = 0; i < HD_; i++) { d1 += lq1[i] * lk1[i]; d2 += lq2[i] * lk2[i]; }
        g_lam = expf(d1) - expf(d2) + 0.8f;
    }
}

// ---------------------------------------------------------------------------
// Tensor-core flash attention, single-pass fp16 (unchanged from R8)
// ---------------------------------------------------------------------------
#define SQ_OFF 0
#define SK_OFF 10240
#define SV_OFF 20480
#define ATT_SMEM 36864
#define NT_ (S_ / 64)

__global__ void __launch_bounds__(256, 2) attn_mma(
    const __half* __restrict__ q16, const __half* __restrict__ vt16,
    float* __restrict__ O1, float* __restrict__ O2)
{
    extern __shared__ __align__(16) uint8_t smem[];
    const uint32_t sbase = smem_to_u32(smem);
    const int tid = threadIdx.x, lane = tid & 31, wr = tid >> 5;
    const int bh = blockIdx.y, b = bh >> 4, h = bh & 15;
    const int half = blockIdx.z, d0 = half << 5;
    const int q0 = blockIdx.x * 128;

    const size_t qkoff = (size_t)b * S_ * QKV_N + h * HD_ + d0;

#pragma unroll
    for (int rep = 0; rep < 2; rep++) {
        int idx = tid + rep * 256;
        int row = idx >> 2, ch = idx & 3;
        size_t g = qkoff + (size_t)(q0 + row) * QKV_N + ch * 8;
        CP16(sbase + SQ_OFF + (uint32_t)(row * 80 + ch * 16), q16 + g);
    }

    auto issue_tile = [&](int t, int stg) {
        uint32_t kb = sbase + SK_OFF + stg * 5120;
        {
            int row = tid >> 2, ch = tid & 3;
            size_t g = qkoff + (size_t)E_ + (size_t)(t * 64 + row) * QKV_N + ch * 8;
            CP16(kb + (uint32_t)(row * 80 + ch * 16), q16 + g);
        }
        uint32_t vb = sbase + SV_OFF + stg * 8192;
#pragma unroll
        for (int rep = 0; rep < 2; rep++) {
            int idx = tid + rep * 256;
            int vrow = idx >> 3, vch = idx & 7;
            size_t g = (size_t)(bh * HD_ + vrow) * S_ + t * 64 + vch * 8;
            CP16(vb + SMEM_SWIZZLE_128B((uint32_t)(vrow * 128 + vch * 16)), vt16 + g);
        }
        CP_COMMIT();
    };

    issue_tile(0, 0);
    issue_tile(1, 1);

    float o[8][4];
#pragma unroll
    for (int j = 0; j < 8; j++)
#pragma unroll
        for (int r = 0; r < 4; r++) o[j][r] = 0.f;
    float m0 = -1e30f, m1 = -1e30f, l0 = 0.f, l1 = 0.f;
    uint32_t ah[2][4];

    const float CSC = 0.125f * 1.4426950408889634f;

    for (int t = 0; t < NT_; t++) {
        if (t < NT_ - 1) asm volatile("cp.async.wait_group 1;");
        else             asm volatile("cp.async.wait_group 0;");
        __syncthreads();

        if (t == 0) {
#pragma unroll
            for (int ks = 0; ks < 2; ks++) {
                uint32_t ra = sbase + SQ_OFF + (uint32_t)((wr * 16 + (lane & 15)) * 80
                              + (ks * 16 + ((lane >> 4) << 3)) * 2);
                LDSM4(ah[ks], ra);
            }
        }

        float s[8][4];
#pragma unroll
        for (int j = 0; j < 8; j++)
#pragma unroll
            for (int r = 0; r < 4; r++) s[j][r] = 0.f;

        const uint32_t kb = sbase + SK_OFF + (t & 1) * 5120;
#pragma unroll
        for (int ks = 0; ks < 2; ks++) {
#pragma unroll
            for (int jp = 0; jp < 4; jp++) {
                uint32_t ra = kb + (uint32_t)((jp * 16 + ((lane >> 4) << 3) + (lane & 7)) * 80
                              + (ks * 16 + (((lane >> 3) & 1) << 3)) * 2);
                uint32_t kh4[4];
                LDSM4(kh4, ra);
                MMAF16(s[jp * 2],     ah[ks], kh4[0], kh4[1]);
                MMAF16(s[jp * 2 + 1], ah[ks], kh4[2], kh4[3]);
            }
        }

        float mx0 = -1e30f, mx1 = -1e30f;
#pragma unroll
        for (int j = 0; j < 8; j++) {
            mx0 = fmaxf(mx0, fmaxf(s[j][0], s[j][1]));
            mx1 = fmaxf(mx1, fmaxf(s[j][2], s[j][3]));
        }
        mx0 = fmaxf(mx0, __shfl_xor_sync(0xffffffffu, mx0, 1));
        mx0 = fmaxf(mx0, __shfl_xor_sync(0xffffffffu, mx0, 2));
        mx1 = fmaxf(mx1, __shfl_xor_sync(0xffffffffu, mx1, 1));
        mx1 = fmaxf(mx1, __shfl_xor_sync(0xffffffffu, mx1, 2));
        const float nm0 = fmaxf(m0, mx0 * CSC), nm1 = fmaxf(m1, mx1 * CSC);
        const float sc0 = exp2f(m0 - nm0), sc1 = exp2f(m1 - nm1);
        m0 = nm0; m1 = nm1;
        l0 *= sc0; l1 *= sc1;
#pragma unroll
        for (int j = 0; j < 8; j++) {
            o[j][0] *= sc0; o[j][1] *= sc0; o[j][2] *= sc1; o[j][3] *= sc1;
        }

        uint32_t pah[4][4];
#pragma unroll
        for (int kp = 0; kp < 4; kp++) {
#pragma unroll
            for (int fi = 0; fi < 2; fi++) {
                const int jf = kp * 2 + fi;
                float p0 = exp2f(fmaf(s[jf][0], CSC, -nm0));
                float p1 = exp2f(fmaf(s[jf][1], CSC, -nm0));
                float p2 = exp2f(fmaf(s[jf][2], CSC, -nm1));
                float p3 = exp2f(fmaf(s[jf][3], CSC, -nm1));
                l0 += p0 + p1; l1 += p2 + p3;
                PACKH(pah[kp][fi * 2],     p0, p1);
                PACKH(pah[kp][fi * 2 + 1], p2, p3);
            }
        }

        const uint32_t vb = sbase + SV_OFF + (t & 1) * 8192;
#pragma unroll
        for (int kp = 0; kp < 4; kp++) {
#pragma unroll
            for (int jn = 0; jn < 4; jn++) {
                uint32_t va = vb + SMEM_SWIZZLE_128B(
                    (uint32_t)((jn * 16 + ((lane >> 4) << 3) + (lane & 7)) * 128
                               + (kp * 16 + (((lane >> 3) & 1) << 3)) * 2));
                uint32_t vh4[4];
                LDSM4(vh4, va);
                MMAF16(o[jn * 2],     pah[kp], vh4[0], vh4[1]);
                MMAF16(o[jn * 2 + 1], pah[kp], vh4[2], vh4[3]);
            }
        }
        __syncthreads();
        if (t + 2 < NT_) issue_tile(t + 2, t & 1);
    }

    l0 += __shfl_xor_sync(0xffffffffu, l0, 1);
    l0 += __shfl_xor_sync(0xffffffffu, l0, 2);
    l1 += __shfl_xor_sync(0xffffffffu, l1, 1);
    l1 += __shfl_xor_sync(0xffffffffu, l1, 2);
    const float inv0 = 1.f / l0, inv1 = 1.f / l1;
    const int g = lane >> 2, tq = lane & 3;
    float* Op = (half ? O2 : O1) + ((size_t)bh * S_ + q0 + wr * 16) * HD_;
#pragma unroll
    for (int jf = 0; jf < 8; jf++) {
        int col = jf * 8 + tq * 2;
        *(float2*)(Op + (size_t)g * HD_ + col) =
            make_float2(o[jf][0] * inv0, o[jf][1] * inv0);
        *(float2*)(Op + (size_t)(g + 8) * HD_ + col) =
            make_float2(o[jf][2] * inv1, o[jf][3] * inv1);
    }
}

// ---------------------------------------------------------------------------
// Combine + RMSNorm + scrambled reshape -> fp16 (SMEM-transposed)
// ---------------------------------------------------------------------------
__global__ __launch_bounds__(256) void combine_kernel(
    const float* __restrict__ O1, const float* __restrict__ O2,
    const float* __restrict__ normw, __half* __restrict__ X2)
{
    __shared__ ushort smh[64][40];

    const int bh = blockIdx.y, b = bh >> 4, h = bh & 15;
    const int s0 = blockIdx.x * 32;
    const int tid = threadIdx.x;
    const int sr = tid >> 3;
    const int dp = (tid & 7) * 8;

    const float lam = g_lam;
    const size_t rbase = ((size_t)bh * S_ + s0 + sr) * HD_ + dp;

    float a[8];
    float ss = 0.f;
#pragma unroll
    for (int c = 0; c < 2; c++) {
        float4 v1 = *(const float4*)(O1 + rbase + c * 4);
        float4 v2 = *(const float4*)(O2 + rbase + c * 4);
        a[c * 4 + 0] = v1.x - lam * v2.x;
        a[c * 4 + 1] = v1.y - lam * v2.y;
        a[c * 4 + 2] = v1.z - lam * v2.z;
        a[c * 4 + 3] = v1.w - lam * v2.w;
#pragma unroll
        for (int j = 0; j < 4; j++) ss += a[c * 4 + j] * a[c * 4 + j];
    }
    ss += __shfl_xor_sync(0xffffffffu, ss, 1);
    ss += __shfl_xor_sync(0xffffffffu, ss, 2);
    ss += __shfl_xor_sync(0xffffffffu, ss, 4);
    const float inv = rsqrtf(ss * (1.f / 64.f) + 1e-6f) * (1.0f - 0.8f);

#pragma unroll
    for (int j = 0; j < 8; j++) {
        float v = a[j] * inv * normw[h * HD_ + dp + j];
        smh[dp + j][sr] = __half_as_ushort(__float2half(v));
    }
    __syncthreads();

    const int dr = tid >> 2, chunk = tid & 3;
    const int shi = s0 >> 10, slo0 = s0 & 1023;
    const size_t obase = (size_t)b * S_ * E_ + (size_t)(dr * 32 + h * 2 + shi) * E_
                       + slo0 + chunk * 8;
    *(uint4*)(X2 + obase) = *(const uint4*)(&smh[dr][chunk * 8]);
}

// ---------------------------------------------------------------------------
// Launch
// ---------------------------------------------------------------------------
extern "C" void kernel_launch(void* const* d_in, const int* in_sizes, int n_in,
                              void* d_out, int out_size)
{
    const float* x     = (const float*)d_in[0];
    const float* w_qkv = (const float*)d_in[1];
    const float* wo    = (const float*)d_in[2];
    const float* lq1   = (const float*)d_in[3];
    const float* lq2   = (const float*)d_in[4];
    const float* lk1   = (const float*)d_in[5];
    const float* lk2   = (const float*)d_in[6];
    const float* normw = (const float*)d_in[7];
    float* out = (float*)d_out;

    float *p_O1, *p_O2;
    cudaGetSymbolAddress((void**)&p_O1, g_O1);
    cudaGetSymbolAddress((void**)&p_O2, g_O2);
    __half *p_x16, *p_q16, *p_vt16, *p_X216, *p_wq16, *p_wo16;
    cudaGetSymbolAddress((void**)&p_x16, g_x16);
    cudaGetSymbolAddress((void**)&p_q16, g_qkv16);
    cudaGetSymbolAddress((void**)&p_vt16, g_vt16);
    cudaGetSymbolAddress((void**)&p_X216, g_X216);
    cudaGetSymbolAddress((void**)&p_wq16, g_wqkvT16);
    cudaGetSymbolAddress((void**)&p_wo16, g_woT16);

    cudaFuncSetAttribute(mma_gemm<0>, cudaFuncAttributeMaxDynamicSharedMemorySize, GEMM_SMEM);
    cudaFuncSetAttribute(mma_gemm<1>, cudaFuncAttributeMaxDynamicSharedMemorySize, GEMM_SMEM);
    cudaFuncSetAttribute(attn_mma, cudaFuncAttributeMaxDynamicSharedMemorySize, ATT_SMEM);

    // 0) fp16 conversions
    tof16_kernel<<<(M_TOK * E_) / (256 * 4), 256>>>(x, p_x16);
    transpose_f16<<<dim3(QKV_N / 32, E_ / 32), 256>>>(w_qkv, p_wq16, E_, QKV_N);
    transpose_f16<<<dim3(E_ / 32, E_ / 32), 256>>>(wo, p_wo16, E_, E_);

    // 1) QKV projection (fp16 single-pass) -> fp16
    mma_gemm<1><<<dim3(QKV_N / 128, M_TOK / 128), 256, GEMM_SMEM>>>(
        p_x16, p_wq16, nullptr, p_q16, M_TOK, QKV_N, E_);

    // 2) V transpose + lambda
    vtrans_kernel<<<dim3(S_ / 32, HD_ / 32, B_ * H_), 256>>>(p_q16, p_vt16);
    lambda_kernel<<<1, 32>>>(lq1, lq2, lk1, lk2);

    // 3) fp16 tensor-core attention, both halves
    attn_mma<<<dim3(S_ / 128, B_ * H_, 2), 256, ATT_SMEM>>>(
        p_q16, p_vt16, p_O1, p_O2);

    // 4) combine + RMSNorm + scrambled reshape -> fp16
    combine_kernel<<<dim3(S_ / 32, B_ * H_), 256>>>(p_O1, p_O2, normw, p_X216);

    // 5) output projection (fp16 single-pass) -> fp32 d_out
    mma_gemm<0><<<dim3(E_ / 128, M_TOK / 128), 256, GEMM_SMEM>>>(
        p_X216, p_wo16, out, nullptr, M_TOK, E_, E_);
}

// round 10
// speedup vs baseline: 9.9294x; 1.0312x over previous
#include <cuda_runtime.h>
#include <cuda_bf16.h>
#include <cuda_fp16.h>
#include <math.h>
#include <stdint.h>

// Problem constants
#define B_  2
#define S_  2048
#define E_  1024
#define H_  16
#define HD_ 64
#define M_TOK (B_ * S_)          // 4096
#define QKV_N (3 * E_)           // 3072

// ---------------------------------------------------------------------------
// Scratch (no allocation allowed -> __device__ globals)
// ---------------------------------------------------------------------------
__device__ float g_O1[B_ * H_ * S_ * HD_];
__device__ float g_O2[B_ * H_ * S_ * HD_];
__device__ float g_lam;
__device__ __half g_x16[M_TOK * E_];              // x fp16
__device__ __half g_qkv16[M_TOK * QKV_N];         // qkv fp16
__device__ __half g_vt16[B_ * H_ * HD_ * S_];     // V^T [b,h,d,s] fp16
__device__ __half g_X216[M_TOK * E_];             // scrambled pre-wo fp16
__device__ __half g_wqkvT16[QKV_N * E_];          // [3072,1024] K-major fp16
__device__ __half g_woT16[E_ * E_];               // [1024,1024] K-major fp16

// ---------------------------------------------------------------------------
// Helpers
// ---------------------------------------------------------------------------
__device__ __forceinline__ uint32_t smem_to_u32(const void* p) {
    uint32_t a;
    asm("{ .reg .u64 tmp; cvta.to.shared.u64 tmp, %1; cvt.u32.u64 %0, tmp; }"
        : "=r"(a) : "l"(p));
    return a;
}
#define CP16(daddr, gptr) \
    asm volatile("cp.async.cg.shared.global [%0], [%1], 16;" \
                 :: "r"(daddr), "l"(gptr))
#define CP_COMMIT() asm volatile("cp.async.commit_group;")
#define LDSM4(r, addr) \
    asm volatile("ldmatrix.sync.aligned.m8n8.x4.shared.b16 {%0,%1,%2,%3}, [%4];" \
                 : "=r"((r)[0]), "=r"((r)[1]), "=r"((r)[2]), "=r"((r)[3]) \
                 : "r"(addr))
#define MMAF16(d, a, b0_, b1_) \
    asm volatile("mma.sync.aligned.m16n8k16.row.col.f32.f16.f16.f32 " \
                 "{%0,%1,%2,%3}, {%4,%5,%6,%7}, {%8,%9}, {%0,%1,%2,%3};" \
                 : "+f"((d)[0]), "+f"((d)[1]), "+f"((d)[2]), "+f"((d)[3]) \
                 : "r"((a)[0]), "r"((a)[1]), "r"((a)[2]), "r"((a)[3]), \
                   "r"(b0_), "r"(b1_))
// pack two fp32 -> f16x2 (lo = first value arg, hi = second)
#define PACKH(r, lo_, hi_) \
    asm("cvt.rn.f16x2.f32 %0, %1, %2;" : "=r"(r) : "f"(hi_), "f"(lo_))
#define SMEM_SWIZZLE_128B(byte_offset) \
    ((byte_offset) ^ (((byte_offset) >> 3) & 0x70))

// ---------------------------------------------------------------------------
// Weight transpose + fp16 convert:  in [K,N] fp32  ->  out [N,K] fp16
// ---------------------------------------------------------------------------
__global__ __launch_bounds__(256) void transpose_f16(
    const float* __restrict__ in, __half* __restrict__ o16, int K, int N)
{
    __shared__ float t[32][33];
    const int tx = threadIdx.x & 31, ty = threadIdx.x >> 5;
    const int n0 = blockIdx.x * 32, k0 = blockIdx.y * 32;
#pragma unroll
    for (int j = 0; j < 32; j += 8)
        t[ty + j][tx] = in[(size_t)(k0 + ty + j) * N + n0 + tx];
    __syncthreads();
#pragma unroll
    for (int j = 0; j < 32; j += 8)
        o16[(size_t)(n0 + ty + j) * K + k0 + tx] = __float2half(t[tx][ty + j]);
}

// ---------------------------------------------------------------------------
// Elementwise fp32 -> fp16 (for x)
// ---------------------------------------------------------------------------
__global__ __launch_bounds__(256) void tof16_kernel(
    const float* __restrict__ in, __half* __restrict__ o16)
{
    int i = (blockIdx.x * 256 + threadIdx.x) * 4;
    float4 v = *(const float4*)(in + i);
    __half2* p = (__half2*)(o16 + i);
    p[0] = __floats2half2_rn(v.x, v.y);
    p[1] = __floats2half2_rn(v.z, v.w);
}

// ---------------------------------------------------------------------------
// V transpose (fp16): qkv v-part [b,s,h,d] -> [b,h,d,s]
// ---------------------------------------------------------------------------
__global__ __launch_bounds__(256) void vtrans_kernel(
    const __half* __restrict__ q16, __half* __restrict__ vt16)
{
    __shared__ __half t[32][33];
    const int bh = blockIdx.z, b = bh >> 4, h = bh & 15;
    const int s0 = blockIdx.x * 32, d0 = blockIdx.y * 32;
    const int tx = threadIdx.x & 31, ty = threadIdx.x >> 5;
#pragma unroll
    for (int j = 0; j < 32; j += 8) {
        size_t ga = (size_t)(b * S_ + s0 + ty + j) * QKV_N + 2 * E_ + h * HD_ + d0 + tx;
        t[ty + j][tx] = q16[ga];
    }
    __syncthreads();
#pragma unroll
    for (int j = 0; j < 32; j += 8) {
        size_t go = (size_t)(bh * HD_ + d0 + ty + j) * S_ + s0 + tx;
        vt16[go] = t[tx][ty + j];
    }
}

// ---------------------------------------------------------------------------
// Tensor-core GEMM, single-pass fp16: C = A @ B^T, fp32 accumulate.
// A: [M,K] fp16 row-major; B: [N,K] fp16 K-major.
// 128x128 tile, BK=64 per stage (halves sync count), 256 thr, 2-stage cp.async.
// PITCH 72 fp16 (144B = 36 words; 36 mod 32 = 4 -> conflict-free LDSM).
// OUTF=0: fp32 C.  OUTF=1: fp16 C.
// ---------------------------------------------------------------------------
#define PITCH 72
#define BUFB  (128 * PITCH * 2)       // 18432 B
#define STAGEB (2 * BUFB)             // 36864 B
#define GEMM_SMEM (2 * STAGEB)        // 73728 B

template <int OUTF>
__global__ void __launch_bounds__(256, 2) mma_gemm(
    const __half* __restrict__ A, const __half* __restrict__ Bm,
    float* __restrict__ C, __half* __restrict__ Cf, int M, int N, int K)
{
    extern __shared__ __align__(16) uint8_t smem[];
    const uint32_t sbase = smem_to_u32(smem);
    const int tid = threadIdx.x, lane = tid & 31, wid = tid >> 5;
    const int wr = wid & 3, wc = wid >> 2;
    const int bm = blockIdx.y * 128, bn = blockIdx.x * 128;
    const int NK = K / 64;

    float acc[2][8][4];
#pragma unroll
    for (int i = 0; i < 2; i++)
#pragma unroll
        for (int j = 0; j < 8; j++)
#pragma unroll
            for (int r = 0; r < 4; r++) acc[i][j][r] = 0.f;

#define ISSUE(kt, stg) do {                                                    \
        uint32_t sb_ = sbase + (stg) * STAGEB;                                 \
        _Pragma("unroll")                                                      \
        for (int hf = 0; hf < 4; hf++) {                                       \
            int c = tid + hf * 256;                                            \
            int row = c >> 3, colc = (c & 7) * 8;                              \
            uint32_t doff = (uint32_t)(row * (PITCH * 2) + colc * 2);          \
            CP16(sb_ + doff, A + (size_t)(bm + row) * K + (kt) * 64 + colc);   \
            CP16(sb_ + BUFB + doff,                                            \
                 Bm + (size_t)(bn + row) * K + (kt) * 64 + colc);              \
        }                                                                      \
        CP_COMMIT();                                                           \
    } while (0)

    ISSUE(0, 0);

    for (int kt = 0; kt < NK; kt++) {
        const int cur = kt & 1;
        if (kt + 1 < NK) {
            ISSUE(kt + 1, (kt + 1) & 1);
            asm volatile("cp.async.wait_group 1;");
        } else {
            asm volatile("cp.async.wait_group 0;");
        }
        __syncthreads();

        const uint32_t sA = sbase + cur * STAGEB;
        const uint32_t sB = sA + BUFB;

#pragma unroll
        for (int ks = 0; ks < 4; ks++) {
            uint32_t ah[2][4];
#pragma unroll
            for (int i = 0; i < 2; i++) {
                uint32_t ra = (uint32_t)((wr * 32 + i * 16 + (lane & 15)) * (PITCH * 2)
                              + (ks * 16 + ((lane >> 4) << 3)) * 2);
                LDSM4(ah[i], sA + ra);
            }
#pragma unroll
            for (int jp = 0; jp < 4; jp++) {
                uint32_t rowb = (uint32_t)(wc * 64 + jp * 16 + ((lane >> 4) << 3) + (lane & 7));
                uint32_t colb = (uint32_t)(ks * 16 + (((lane >> 3) & 1) << 3));
                uint32_t rb = rowb * (PITCH * 2) + colb * 2;
                uint32_t bh4[4];
                LDSM4(bh4, sB + rb);
                MMAF16(acc[0][jp * 2],     ah[0], bh4[0], bh4[1]);
                MMAF16(acc[1][jp * 2],     ah[1], bh4[0], bh4[1]);
                MMAF16(acc[0][jp * 2 + 1], ah[0], bh4[2], bh4[3]);
                MMAF16(acc[1][jp * 2 + 1], ah[1], bh4[2], bh4[3]);
            }
        }
        __syncthreads();
    }

#pragma unroll
    for (int i = 0; i < 2; i++) {
        int mrow = bm + wr * 32 + i * 16 + (lane >> 2);
#pragma unroll
        for (int j = 0; j < 8; j++) {
            int ncol = bn + wc * 64 + j * 8 + (lane & 3) * 2;
            if (OUTF == 0) {
                *(float2*)(C + (size_t)mrow * N + ncol) =
                    make_float2(acc[i][j][0], acc[i][j][1]);
                *(float2*)(C + (size_t)(mrow + 8) * N + ncol) =
                    make_float2(acc[i][j][2], acc[i][j][3]);
            } else {
                *(__half2*)(Cf + (size_t)mrow * N + ncol) =
                    __floats2half2_rn(acc[i][j][0], acc[i][j][1]);
                *(__half2*)(Cf + (size_t)(mrow + 8) * N + ncol) =
                    __floats2half2_rn(acc[i][j][2], acc[i][j][3]);
            }
        }
    }
#undef ISSUE
}

// ---------------------------------------------------------------------------
// Lambda scalar
// ---------------------------------------------------------------------------
__global__ void lambda_kernel(const float* __restrict__ lq1, const float* __restrict__ lq2,
                              const float* __restrict__ lk1, const float* __restrict__ lk2)
{
    if (threadIdx.x == 0) {
        float d1 = 0.f, d2 = 0.f;
        for (int i = 0; i < HD_; i++) { d1 += lq1[i] * lk1[i]; d2 += lq2[i] * lk2[i]; }
        g_lam = expf(d1) - expf(d2) + 0.8f;
    }
}

// ---------------------------------------------------------------------------
// Tensor-core flash attention, single-pass fp16.
// Key tile = 128 keys per stage (two 64-key sub-tiles, identical addressing
// to the proven layout), ONE sync/wait pair per 128-key tile.
// smem: Q[0,10240) | K stages 10240+stg*10240 (sub at +5120)
//       | Vt stages 30720+stg*16384 (sub at +8192)
// ---------------------------------------------------------------------------
#define SQ_OFF 0
#define SK_OFF 10240
#define SV_OFF 30720
#define ATT_SMEM 63488
#define NT_ (S_ / 128)

__global__ void __launch_bounds__(256, 2) attn_mma(
    const __half* __restrict__ q16, const __half* __restrict__ vt16,
    float* __restrict__ O1, float* __restrict__ O2)
{
    extern __shared__ __align__(16) uint8_t smem[];
    const uint32_t sbase = smem_to_u32(smem);
    const int tid = threadIdx.x, lane = tid & 31, wr = tid >> 5;
    const int bh = blockIdx.y, b = bh >> 4, h = bh & 15;
    const int half = blockIdx.z, d0 = half << 5;
    const int q0 = blockIdx.x * 128;

    const size_t qkoff = (size_t)b * S_ * QKV_N + h * HD_ + d0;

#pragma unroll
    for (int rep = 0; rep < 2; rep++) {
        int idx = tid + rep * 256;
        int row = idx >> 2, ch = idx & 3;
        size_t g = qkoff + (size_t)(q0 + row) * QKV_N + ch * 8;
        CP16(sbase + SQ_OFF + (uint32_t)(row * 80 + ch * 16), q16 + g);
    }

    // 128-key tile = two 64-key halves, one commit
    auto issue_tile = [&](int t, int stg) {
        uint32_t kb = sbase + SK_OFF + stg * 10240;
        uint32_t vb = sbase + SV_OFF + stg * 16384;
#pragma unroll
        for (int sub = 0; sub < 2; sub++) {
            {
                int row = tid >> 2, ch = tid & 3;
                size_t g = qkoff + (size_t)E_
                         + (size_t)(t * 128 + sub * 64 + row) * QKV_N + ch * 8;
                CP16(kb + sub * 5120 + (uint32_t)(row * 80 + ch * 16), q16 + g);
            }
#pragma unroll
            for (int rep = 0; rep < 2; rep++) {
                int idx = tid + rep * 256;
                int vrow = idx >> 3, vch = idx & 7;
                size_t g = (size_t)(bh * HD_ + vrow) * S_ + t * 128 + sub * 64 + vch * 8;
                CP16(vb + sub * 8192
                     + SMEM_SWIZZLE_128B((uint32_t)(vrow * 128 + vch * 16)), vt16 + g);
            }
        }
        CP_COMMIT();
    };

    issue_tile(0, 0);
    issue_tile(1, 1);

    float o[8][4];
#pragma unroll
    for (int j = 0; j < 8; j++)
#pragma unroll
        for (int r = 0; r < 4; r++) o[j][r] = 0.f;
    float m0 = -1e30f, m1 = -1e30f, l0 = 0.f, l1 = 0.f;
    uint32_t ah[2][4];

    const float CSC = 0.125f * 1.4426950408889634f;

    for (int t = 0; t < NT_; t++) {
        if (t < NT_ - 1) asm volatile("cp.async.wait_group 1;");
        else             asm volatile("cp.async.wait_group 0;");
        __syncthreads();

        if (t == 0) {
#pragma unroll
            for (int ks = 0; ks < 2; ks++) {
                uint32_t ra = sbase + SQ_OFF + (uint32_t)((wr * 16 + (lane & 15)) * 80
                              + (ks * 16 + ((lane >> 4) << 3)) * 2);
                LDSM4(ah[ks], ra);
            }
        }

#pragma unroll
        for (int sub = 0; sub < 2; sub++) {
            // ---- S = Q K^T (fp16) ----
            float s[8][4];
#pragma unroll
            for (int j = 0; j < 8; j++)
#pragma unroll
                for (int r = 0; r < 4; r++) s[j][r] = 0.f;

            const uint32_t kb = sbase + SK_OFF + (t & 1) * 10240 + sub * 5120;
#pragma unroll
            for (int ks = 0; ks < 2; ks++) {
#pragma unroll
                for (int jp = 0; jp < 4; jp++) {
                    uint32_t ra = kb + (uint32_t)(
                        (jp * 16 + ((lane >> 4) << 3) + (lane & 7)) * 80
                        + (ks * 16 + (((lane >> 3) & 1) << 3)) * 2);
                    uint32_t kh4[4];
                    LDSM4(kh4, ra);
                    MMAF16(s[jp * 2],     ah[ks], kh4[0], kh4[1]);
                    MMAF16(s[jp * 2 + 1], ah[ks], kh4[2], kh4[3]);
                }
            }

            // ---- online softmax ----
            float mx0 = -1e30f, mx1 = -1e30f;
#pragma unroll
            for (int j = 0; j < 8; j++) {
                mx0 = fmaxf(mx0, fmaxf(s[j][0], s[j][1]));
                mx1 = fmaxf(mx1, fmaxf(s[j][2], s[j][3]));
            }
            mx0 = fmaxf(mx0, __shfl_xor_sync(0xffffffffu, mx0, 1));
            mx0 = fmaxf(mx0, __shfl_xor_sync(0xffffffffu, mx0, 2));
            mx1 = fmaxf(mx1, __shfl_xor_sync(0xffffffffu, mx1, 1));
            mx1 = fmaxf(mx1, __shfl_xor_sync(0xffffffffu, mx1, 2));
            const float nm0 = fmaxf(m0, mx0 * CSC), nm1 = fmaxf(m1, mx1 * CSC);
            const float sc0 = exp2f(m0 - nm0), sc1 = exp2f(m1 - nm1);
            m0 = nm0; m1 = nm1;
            l0 *= sc0; l1 *= sc1;
#pragma unroll
            for (int j = 0; j < 8; j++) {
                o[j][0] *= sc0; o[j][1] *= sc0; o[j][2] *= sc1; o[j][3] *= sc1;
            }

            uint32_t pah[4][4];
#pragma unroll
            for (int kp = 0; kp < 4; kp++) {
#pragma unroll
                for (int fi = 0; fi < 2; fi++) {
                    const int jf = kp * 2 + fi;
                    float p0 = exp2f(fmaf(s[jf][0], CSC, -nm0));
                    float p1 = exp2f(fmaf(s[jf][1], CSC, -nm0));
                    float p2 = exp2f(fmaf(s[jf][2], CSC, -nm1));
                    float p3 = exp2f(fmaf(s[jf][3], CSC, -nm1));
                    l0 += p0 + p1; l1 += p2 + p3;
                    PACKH(pah[kp][fi * 2],     p0, p1);
                    PACKH(pah[kp][fi * 2 + 1], p2, p3);
                }
            }

            // ---- O += P V (fp16) ----
            const uint32_t vb = sbase + SV_OFF + (t & 1) * 16384 + sub * 8192;
#pragma unroll
            for (int kp = 0; kp < 4; kp++) {
#pragma unroll
                for (int jn = 0; jn < 4; jn++) {
                    uint32_t va = vb + SMEM_SWIZZLE_128B(
                        (uint32_t)((jn * 16 + ((lane >> 4) << 3) + (lane & 7)) * 128
                                   + (kp * 16 + (((lane >> 3) & 1) << 3)) * 2));
                    uint32_t vh4[4];
                    LDSM4(vh4, va);
                    MMAF16(o[jn * 2],     pah[kp], vh4[0], vh4[1]);
                    MMAF16(o[jn * 2 + 1], pah[kp], vh4[2], vh4[3]);
                }
            }
        }
        __syncthreads();
        if (t + 2 < NT_) issue_tile(t + 2, t & 1);
    }

    l0 += __shfl_xor_sync(0xffffffffu, l0, 1);
    l0 += __shfl_xor_sync(0xffffffffu, l0, 2);
    l1 += __shfl_xor_sync(0xffffffffu, l1, 1);
    l1 += __shfl_xor_sync(0xffffffffu, l1, 2);
    const float inv0 = 1.f / l0, inv1 = 1.f / l1;
    const int g = lane >> 2, tq = lane & 3;
    float* Op = (half ? O2 : O1) + ((size_t)bh * S_ + q0 + wr * 16) * HD_;
#pragma unroll
    for (int jf = 0; jf < 8; jf++) {
        int col = jf * 8 + tq * 2;
        *(float2*)(Op + (size_t)g * HD_ + col) =
            make_float2(o[jf][0] * inv0, o[jf][1] * inv0);
        *(float2*)(Op + (size_t)(g + 8) * HD_ + col) =
            make_float2(o[jf][2] * inv1, o[jf][3] * inv1);
    }
}

// ---------------------------------------------------------------------------
// Combine + RMSNorm + scrambled reshape -> fp16 (SMEM-transposed)
// ---------------------------------------------------------------------------
__global__ __launch_bounds__(256) void combine_kernel(
    const float* __restrict__ O1, const float* __restrict__ O2,
    const float* __restrict__ normw, __half* __restrict__ X2)
{
    __shared__ ushort smh[64][40];

    const int bh = blockIdx.y, b = bh >> 4, h = bh & 15;
    const int s0 = blockIdx.x * 32;
    const int tid = threadIdx.x;
    const int sr = tid >> 3;
    const int dp = (tid & 7) * 8;

    const float lam = g_lam;
    const size_t rbase = ((size_t)bh * S_ + s0 + sr) * HD_ + dp;

    float a[8];
    float ss = 0.f;
#pragma unroll
    for (int c = 0; c < 2; c++) {
        float4 v1 = *(const float4*)(O1 + rbase + c * 4);
        float4 v2 = *(const float4*)(O2 + rbase + c * 4);
        a[c * 4 + 0] = v1.x - lam * v2.x;
        a[c * 4 + 1] = v1.y - lam * v2.y;
        a[c * 4 + 2] = v1.z - lam * v2.z;
        a[c * 4 + 3] = v1.w - lam * v2.w;
#pragma unroll
        for (int j = 0; j < 4; j++) ss += a[c * 4 + j] * a[c * 4 + j];
    }
    ss += __shfl_xor_sync(0xffffffffu, ss, 1);
    ss += __shfl_xor_sync(0xffffffffu, ss, 2);
    ss += __shfl_xor_sync(0xffffffffu, ss, 4);
    const float inv = rsqrtf(ss * (1.f / 64.f) + 1e-6f) * (1.0f - 0.8f);

#pragma unroll
    for (int j = 0; j < 8; j++) {
        float v = a[j] * inv * normw[h * HD_ + dp + j];
        smh[dp + j][sr] = __half_as_ushort(__float2half(v));
    }
    __syncthreads();

    const int dr = tid >> 2, chunk = tid & 3;
    const int shi = s0 >> 10, slo0 = s0 & 1023;
    const size_t obase = (size_t)b * S_ * E_ + (size_t)(dr * 32 + h * 2 + shi) * E_
                       + slo0 + chunk * 8;
    *(uint4*)(X2 + obase) = *(const uint4*)(&smh[dr][chunk * 8]);
}

// ---------------------------------------------------------------------------
// Launch
// ---------------------------------------------------------------------------
extern "C" void kernel_launch(void* const* d_in, const int* in_sizes, int n_in,
                              void* d_out, int out_size)
{
    const float* x     = (const float*)d_in[0];
    const float* w_qkv = (const float*)d_in[1];
    const float* wo    = (const float*)d_in[2];
    const float* lq1   = (const float*)d_in[3];
    const float* lq2   = (const float*)d_in[4];
    const float* lk1   = (const float*)d_in[5];
    const float* lk2   = (const float*)d_in[6];
    const float* normw = (const float*)d_in[7];
    float* out = (float*)d_out;

    float *p_O1, *p_O2;
    cudaGetSymbolAddress((void**)&p_O1, g_O1);
    cudaGetSymbolAddress((void**)&p_O2, g_O2);
    __half *p_x16, *p_q16, *p_vt16, *p_X216, *p_wq16, *p_wo16;
    cudaGetSymbolAddress((void**)&p_x16, g_x16);
    cudaGetSymbolAddress((void**)&p_q16, g_qkv16);
    cudaGetSymbolAddress((void**)&p_vt16, g_vt16);
    cudaGetSymbolAddress((void**)&p_X216, g_X216);
    cudaGetSymbolAddress((void**)&p_wq16, g_wqkvT16);
    cudaGetSymbolAddress((void**)&p_wo16, g_woT16);

    cudaFuncSetAttribute(mma_gemm<0>, cudaFuncAttributeMaxDynamicSharedMemorySize, GEMM_SMEM);
    cudaFuncSetAttribute(mma_gemm<1>, cudaFuncAttributeMaxDynamicSharedMemorySize, GEMM_SMEM);
    cudaFuncSetAttribute(attn_mma, cudaFuncAttributeMaxDynamicSharedMemorySize, ATT_SMEM);

    // 0) fp16 conversions
    tof16_kernel<<<(M_TOK * E_) / (256 * 4), 256>>>(x, p_x16);
    transpose_f16<<<dim3(QKV_N / 32, E_ / 32), 256>>>(w_qkv, p_wq16, E_, QKV_N);
    transpose_f16<<<dim3(E_ / 32, E_ / 32), 256>>>(wo, p_wo16, E_, E_);

    // 1) QKV projection (fp16 single-pass) -> fp16
    mma_gemm<1><<<dim3(QKV_N / 128, M_TOK / 128), 256, GEMM_SMEM>>>(
        p_x16, p_wq16, nullptr, p_q16, M_TOK, QKV_N, E_);

    // 2) V transpose + lambda
    vtrans_kernel<<<dim3(S_ / 32, HD_ / 32, B_ * H_), 256>>>(p_q16, p_vt16);
    lambda_kernel<<<1, 32>>>(lq1, lq2, lk1, lk2);

    // 3) fp16 tensor-core attention, both halves
    attn_mma<<<dim3(S_ / 128, B_ * H_, 2), 256, ATT_SMEM>>>(
        p_q16, p_vt16, p_O1, p_O2);

    // 4) combine + RMSNorm + scrambled reshape -> fp16
    combine_kernel<<<dim3(S_ / 32, B_ * H_), 256>>>(p_O1, p_O2, normw, p_X216);

    // 5) output projection (fp16 single-pass) -> fp32 d_out
    mma_gemm<0><<<dim3(E_ / 128, M_TOK / 128), 256, GEMM_SMEM>>>(
        p_X216, p_wo16, out, nullptr, M_TOK, E_, E_);
}